// round 6
// baseline (speedup 1.0000x reference)
#include <cuda_runtime.h>
#include <math.h>
#include <stdint.h>

// Problem constants
#define NN 50000
#define EE 800000
#define F_IN 512
#define HH 128
#define CC 16
#define LD3H 384   // 3*H

// ---------------- device scratch (static, no allocations) ----------------
__device__ int   g_count[NN];
__device__ int   g_rowptr[NN + 1];
__device__ int   g_pos[NN];
__device__ int   g_state[64];
__device__ int   g_col[EE];
__device__ float g_val[EE];
__device__ float g_bufA[(size_t)NN * LD3H];
__device__ float g_bufB[(size_t)NN * LD3H];
__device__ float g_bufC[(size_t)NN * LD3H];
__device__ float g_bufD[(size_t)NN * LD3H];
__device__ float g_w1r[3 * F_IN * HH];           // tf32-rounded w1
__device__ float g_w2r[3 * LD3H * HH];           // tf32-rounded w2

// ---------------- helpers ----------------
__device__ __forceinline__ float f2tf_f(float f) {
    uint32_t u; asm("cvt.rna.tf32.f32 %0, %1;" : "=r"(u) : "f"(f));
    return __uint_as_float(u);
}
__device__ __forceinline__ uint32_t f2tf(float f) {
    uint32_t u; asm("cvt.rna.tf32.f32 %0, %1;" : "=r"(u) : "f"(f)); return u;
}

__device__ __forceinline__ void mma_tf32(float* c, const uint32_t* a, const uint32_t* b) {
    asm volatile(
        "mma.sync.aligned.m16n8k8.row.col.f32.tf32.tf32.f32 "
        "{%0,%1,%2,%3}, {%4,%5,%6,%7}, {%8,%9}, {%0,%1,%2,%3};\n"
        : "+f"(c[0]), "+f"(c[1]), "+f"(c[2]), "+f"(c[3])
        : "r"(a[0]), "r"(a[1]), "r"(a[2]), "r"(a[3]), "r"(b[0]), "r"(b[1]));
}

__device__ __forceinline__ void cpa16(uint32_t dst_smem, const void* src, int valid) {
    asm volatile("cp.async.cg.shared.global [%0], [%1], 16, %2;\n"
                 :: "r"(dst_smem), "l"(src), "r"(valid ? 16 : 0));
}
__device__ __forceinline__ void cpa_commit() { asm volatile("cp.async.commit_group;\n"); }
__device__ __forceinline__ void cpa_wait0()  { asm volatile("cp.async.wait_group 0;\n"); }

// ---------------- weight round to tf32 ----------------
#define NW14  (3 * F_IN * HH / 4)              // 49,152
#define NW24  (3 * LD3H * HH / 4)              // 36,864
__global__ void k_roundw(const float4* __restrict__ w1, const float4* __restrict__ w2)
{
    int i = blockIdx.x * blockDim.x + threadIdx.x;
    if (i < NW14) {
        float4 v = w1[i];
        v.x = f2tf_f(v.x); v.y = f2tf_f(v.y); v.z = f2tf_f(v.z); v.w = f2tf_f(v.w);
        ((float4*)g_w1r)[i] = v;
    } else if (i < NW14 + NW24) {
        int j = i - NW14;
        float4 v = w2[j];
        v.x = f2tf_f(v.x); v.y = f2tf_f(v.y); v.z = f2tf_f(v.z); v.w = f2tf_f(v.w);
        ((float4*)g_w2r)[j] = v;
    }
}

// ---------------- CSR build ----------------
__global__ void k_zero_counts() {
    int i = blockIdx.x * blockDim.x + threadIdx.x;
    if (i < NN) g_count[i] = 0;
    if (i < 64) g_state[i] = -1;
}

__global__ void k_count(const int* __restrict__ idx) {
    int e = blockIdx.x * blockDim.x + threadIdx.x;
    if (e < EE) atomicAdd(&g_count[idx[e]], 1);
}

#define SCAN_B 1024
__global__ void k_scanfused() {
    __shared__ int s[SCAN_B];
    __shared__ int pfx;
    int t = threadIdx.x;
    int b = blockIdx.x;
    int i = b * SCAN_B + t;
    int v = (i < NN) ? g_count[i] : 0;
    s[t] = v;
    __syncthreads();
    #pragma unroll
    for (int o = 1; o < SCAN_B; o <<= 1) {
        int u = (t >= o) ? s[t - o] : 0;
        __syncthreads();
        s[t] += u;
        __syncthreads();
    }
    if (t == 0) {
        int total = s[SCAN_B - 1];
        int p = 0;
        if (b > 0) {
            while ((p = atomicAdd(&g_state[b - 1], 0)) < 0) {}
        }
        pfx = p;
        __threadfence();
        atomicExch(&g_state[b], p + total);
    }
    __syncthreads();
    if (i < NN) {
        int e = pfx + s[t] - v;
        g_rowptr[i] = e;
        g_pos[i] = e;
    }
    if (i == 0) g_rowptr[NN] = EE;
}

__global__ void k_scatter(const int* __restrict__ idx, const float* __restrict__ vals) {
    int e = blockIdx.x * blockDim.x + threadIdx.x;
    if (e < EE) {
        int r = idx[e];
        int p = atomicAdd(&g_pos[r], 1);
        g_col[p] = idx[EE + e];
        g_val[p] = vals[e];
    }
}

// ---------------- tf32 tensor-core GEMM, cp.async double-buffered ----------------
// n-block nb = blockIdx.x + nb_off; A cvt'd in mainloop; B pre-rounded.
#define LDA_S 36
#define LDB_S 136
#define A_BUF_W (128 * LDA_S)
#define B_BUF_W (32 * LDB_S)
#define GEMM_SMEM_BYTES ((2 * A_BUF_W + 2 * B_BUF_W) * 4)

__global__ __launch_bounds__(256, 2)
void k_gemm_tc(const float* __restrict__ A, int lda,
               const float* __restrict__ Bbase, int bstride,
               const float* __restrict__ bias,      // [3*128] or null
               float* __restrict__ C0, float* __restrict__ C1, float* __restrict__ C2,
               int M, int K, int do_relu, int nb_off, int accum)
{
    extern __shared__ uint32_t smem[];
    uint32_t* As = smem;
    uint32_t* Bs = smem + 2 * A_BUF_W;

    const int nb = blockIdx.x + nb_off;
    const float* B = Bbase + (size_t)nb * bstride;
    float* C = (nb == 0) ? C0 : ((nb == 1) ? C1 : C2);
    const float* bi = bias ? (bias + nb * 128) : (const float*)0;

    const int m0   = blockIdx.y * 128;
    const int tid  = threadIdx.x;
    const int lane = tid & 31;
    const int wid  = tid >> 5;
    const int wm0  = (wid & 1) * 64;
    const int wn0  = (wid >> 1) * 32;
    const int gp   = lane >> 2;
    const int tg   = lane & 3;

    float acc[4][4][4];
    #pragma unroll
    for (int i = 0; i < 4; i++)
        #pragma unroll
        for (int j = 0; j < 4; j++)
            #pragma unroll
            for (int q = 0; q < 4; q++) acc[i][j][q] = 0.f;

    const int nk = K >> 5;

    auto stage = [&](int kt, int buf) {
        const int k0 = kt << 5;
        uint32_t abase = (uint32_t)__cvta_generic_to_shared(As + buf * A_BUF_W);
        uint32_t bbase = (uint32_t)__cvta_generic_to_shared(Bs + buf * B_BUF_W);
        #pragma unroll
        for (int s = 0; s < 4; s++) {
            int idx = s * 256 + tid;
            int r = idx >> 3;
            int c = (idx & 7) * 4;
            int gr = m0 + r;
            int ok = gr < M;
            int srow = ok ? gr : (M - 1);
            cpa16(abase + (r * LDA_S + c) * 4, A + (size_t)srow * lda + k0 + c, ok);
        }
        #pragma unroll
        for (int s = 0; s < 4; s++) {
            int idx = s * 256 + tid;
            int r = idx >> 5;
            int c = (idx & 31) * 4;
            cpa16(bbase + (r * LDB_S + c) * 4, B + (size_t)(k0 + r) * 128 + c, 1);
        }
        cpa_commit();
    };

    stage(0, 0);

    for (int kt = 0; kt < nk; kt++) {
        cpa_wait0();
        __syncthreads();
        if (kt + 1 < nk) stage(kt + 1, (kt + 1) & 1);

        const uint32_t* Ab = As + (kt & 1) * A_BUF_W;
        const uint32_t* Bb = Bs + (kt & 1) * B_BUF_W;

        #pragma unroll
        for (int ks = 0; ks < 4; ks++) {
            uint32_t af[4][4], bf[4][2];
            const int kk = ks * 8 + tg;
            #pragma unroll
            for (int i = 0; i < 4; i++) {
                int r = wm0 + i * 16 + gp;
                af[i][0] = f2tf(__uint_as_float(Ab[r * LDA_S + kk]));
                af[i][1] = f2tf(__uint_as_float(Ab[(r + 8) * LDA_S + kk]));
                af[i][2] = f2tf(__uint_as_float(Ab[r * LDA_S + kk + 4]));
                af[i][3] = f2tf(__uint_as_float(Ab[(r + 8) * LDA_S + kk + 4]));
            }
            #pragma unroll
            for (int j = 0; j < 4; j++) {
                int n = wn0 + j * 8 + gp;
                bf[j][0] = Bb[kk * LDB_S + n];
                bf[j][1] = Bb[(kk + 4) * LDB_S + n];
            }
            #pragma unroll
            for (int i = 0; i < 4; i++)
                #pragma unroll
                for (int j = 0; j < 4; j++)
                    mma_tf32(acc[i][j], af[i], bf[j]);
        }
        __syncthreads();
    }

    #pragma unroll
    for (int i = 0; i < 4; i++) {
        #pragma unroll
        for (int rr = 0; rr < 2; rr++) {
            int row = m0 + wm0 + i * 16 + gp + rr * 8;
            if (row >= M) continue;
            #pragma unroll
            for (int j = 0; j < 4; j++) {
                int col = wn0 + j * 8 + 2 * tg;
                float* cp = C + (size_t)row * LD3H + col;
                float2 v;
                v.x = acc[i][j][rr * 2 + 0];
                v.y = acc[i][j][rr * 2 + 1];
                if (accum) { float2 o = *(float2*)cp; v.x += o.x; v.y += o.y; }
                if (bi) { v.x += bi[col]; v.y += bi[col + 1]; }
                if (do_relu) { v.x = fmaxf(v.x, 0.f); v.y = fmaxf(v.y, 0.f); }
                *(float2*)cp = v;
            }
        }
    }
}

// ---------------- SpMM (CSR gather) ----------------
__global__ void k_spmm256(const float* __restrict__ src,
                          float* __restrict__ dstA, float* __restrict__ dstB)
{
    int warp = (blockIdx.x * blockDim.x + threadIdx.x) >> 5;
    int lane = threadIdx.x & 31;
    if (warp >= NN) return;
    int s = g_rowptr[warp];
    int e = g_rowptr[warp + 1];
    float4 a0 = make_float4(0.f, 0.f, 0.f, 0.f);
    float4 a1 = make_float4(0.f, 0.f, 0.f, 0.f);
    int p = s;
    for (; p + 1 < e; p += 2) {
        int   c0 = g_col[p],   c1 = g_col[p + 1];
        float v0 = g_val[p],   v1 = g_val[p + 1];
        const float* r0 = src + (size_t)c0 * LD3H + lane * 4;
        const float* r1 = src + (size_t)c1 * LD3H + lane * 4;
        float4 h0 = *(const float4*)r0;
        float4 h1 = *(const float4*)(r0 + 128);
        float4 g0 = *(const float4*)r1;
        float4 g1 = *(const float4*)(r1 + 128);
        a0.x = fmaf(v0, h0.x, a0.x); a0.y = fmaf(v0, h0.y, a0.y);
        a0.z = fmaf(v0, h0.z, a0.z); a0.w = fmaf(v0, h0.w, a0.w);
        a1.x = fmaf(v0, h1.x, a1.x); a1.y = fmaf(v0, h1.y, a1.y);
        a1.z = fmaf(v0, h1.z, a1.z); a1.w = fmaf(v0, h1.w, a1.w);
        a0.x = fmaf(v1, g0.x, a0.x); a0.y = fmaf(v1, g0.y, a0.y);
        a0.z = fmaf(v1, g0.z, a0.z); a0.w = fmaf(v1, g0.w, a0.w);
        a1.x = fmaf(v1, g1.x, a1.x); a1.y = fmaf(v1, g1.y, a1.y);
        a1.z = fmaf(v1, g1.z, a1.z); a1.w = fmaf(v1, g1.w, a1.w);
    }
    if (p < e) {
        int c0 = g_col[p];
        float v0 = g_val[p];
        const float* r0 = src + (size_t)c0 * LD3H + lane * 4;
        float4 h0 = *(const float4*)r0;
        float4 h1 = *(const float4*)(r0 + 128);
        a0.x = fmaf(v0, h0.x, a0.x); a0.y = fmaf(v0, h0.y, a0.y);
        a0.z = fmaf(v0, h0.z, a0.z); a0.w = fmaf(v0, h0.w, a0.w);
        a1.x = fmaf(v0, h1.x, a1.x); a1.y = fmaf(v0, h1.y, a1.y);
        a1.z = fmaf(v0, h1.z, a1.z); a1.w = fmaf(v0, h1.w, a1.w);
    }
    *(float4*)(dstA + (size_t)warp * LD3H + lane * 4) = a0;
    *(float4*)(dstB + (size_t)warp * LD3H + lane * 4) = a1;
}

__global__ void k_spmm128(const float* __restrict__ src, float* __restrict__ dst)
{
    int warp = (blockIdx.x * blockDim.x + threadIdx.x) >> 5;
    int lane = threadIdx.x & 31;
    if (warp >= NN) return;
    int s = g_rowptr[warp];
    int e = g_rowptr[warp + 1];
    float4 a0 = make_float4(0.f, 0.f, 0.f, 0.f);
    int p = s;
    for (; p + 1 < e; p += 2) {
        int   c0 = g_col[p],   c1 = g_col[p + 1];
        float v0 = g_val[p],   v1 = g_val[p + 1];
        float4 h0 = *(const float4*)(src + (size_t)c0 * LD3H + lane * 4);
        float4 h1 = *(const float4*)(src + (size_t)c1 * LD3H + lane * 4);
        a0.x = fmaf(v0, h0.x, a0.x); a0.y = fmaf(v0, h0.y, a0.y);
        a0.z = fmaf(v0, h0.z, a0.z); a0.w = fmaf(v0, h0.w, a0.w);
        a0.x = fmaf(v1, h1.x, a0.x); a0.y = fmaf(v1, h1.y, a0.y);
        a0.z = fmaf(v1, h1.z, a0.z); a0.w = fmaf(v1, h1.w, a0.w);
    }
    if (p < e) {
        int c0 = g_col[p];
        float v0 = g_val[p];
        float4 h0 = *(const float4*)(src + (size_t)c0 * LD3H + lane * 4);
        a0.x = fmaf(v0, h0.x, a0.x); a0.y = fmaf(v0, h0.y, a0.y);
        a0.z = fmaf(v0, h0.z, a0.z); a0.w = fmaf(v0, h0.w, a0.w);
    }
    *(float4*)(dst + (size_t)warp * LD3H + lane * 4) = a0;
}

// ---------------- final ----------------
#define FROWS 8
__global__ __launch_bounds__(128)
void k_final(const float* __restrict__ g,
             const float* __restrict__ b2,
             const float* __restrict__ wf,
             const float* __restrict__ bfv,
             float* __restrict__ out)
{
    __shared__ float wfs[LD3H * CC];
    __shared__ float gs[FROWS][LD3H];
    int tid = threadIdx.x;
    for (int i = tid; i < LD3H * CC; i += 128) wfs[i] = wf[i];
    int row0 = blockIdx.x * FROWS;
    for (int i = tid; i < FROWS * LD3H; i += 128) {
        int r = i / LD3H, k = i % LD3H;
        int gr = row0 + r;
        gs[r][k] = (gr < NN) ? g[(size_t)gr * LD3H + k] + b2[k] : 0.f;
    }
    __syncthreads();

    int r = tid >> 4;
    int c = tid & 15;
    float acc = bfv[c];
    #pragma unroll 8
    for (int k = 0; k < LD3H; k++) acc = fmaf(gs[r][k], wfs[k * CC + c], acc);

    float m = acc;
    #pragma unroll
    for (int o = 8; o >= 1; o >>= 1) m = fmaxf(m, __shfl_xor_sync(0xffffffffu, m, o, 16));
    float ex = __expf(acc - m);
    float s = ex;
    #pragma unroll
    for (int o = 8; o >= 1; o >>= 1) s += __shfl_xor_sync(0xffffffffu, s, o, 16);
    int gr = row0 + r;
    if (gr < NN) out[gr * CC + c] = acc - m - logf(s);
}

// ---------------- launch ----------------
extern "C" void kernel_launch(void* const* d_in, const int* in_sizes, int n_in,
                              void* d_out, int out_size)
{
    const float* x   = (const float*)d_in[0];
    const int*   adj = (const int*)d_in[1];
    const float* av  = (const float*)d_in[2];
    const float* w1  = (const float*)d_in[3];
    const float* b1  = (const float*)d_in[4];
    const float* w2  = (const float*)d_in[5];
    const float* b2  = (const float*)d_in[6];
    const float* wf  = (const float*)d_in[7];
    const float* bf  = (const float*)d_in[8];
    float* out = (float*)d_out;

    float *bufA, *bufB, *bufC, *bufD, *w1r, *w2r;
    cudaGetSymbolAddress((void**)&bufA, g_bufA);
    cudaGetSymbolAddress((void**)&bufB, g_bufB);
    cudaGetSymbolAddress((void**)&bufC, g_bufC);
    cudaGetSymbolAddress((void**)&bufD, g_bufD);
    cudaGetSymbolAddress((void**)&w1r,  g_w1r);
    cudaGetSymbolAddress((void**)&w2r,  g_w2r);

    cudaFuncSetAttribute(k_gemm_tc, cudaFuncAttributeMaxDynamicSharedMemorySize,
                         GEMM_SMEM_BYTES);

    static cudaStream_t s1 = 0, s2 = 0;
    static cudaEvent_t evFork = 0, evW = 0, evCSR = 0, evSp1a = 0, evS1d = 0;
    if (!s1) {
        cudaStreamCreateWithFlags(&s1, cudaStreamNonBlocking);
        cudaStreamCreateWithFlags(&s2, cudaStreamNonBlocking);
        cudaEventCreateWithFlags(&evFork, cudaEventDisableTiming);
        cudaEventCreateWithFlags(&evW,    cudaEventDisableTiming);
        cudaEventCreateWithFlags(&evCSR,  cudaEventDisableTiming);
        cudaEventCreateWithFlags(&evSp1a, cudaEventDisableTiming);
        cudaEventCreateWithFlags(&evS1d,  cudaEventDisableTiming);
    }

    const int nscan = (NN + SCAN_B - 1) / SCAN_B;   // 49
    const int mtiles = (NN + 127) / 128;            // 391
    const int sblocks = (NN + 3) / 4;

    // ---- fork ----
    cudaEventRecord(evFork, 0);
    cudaStreamWaitEvent(s1, evFork, 0);
    cudaStreamWaitEvent(s2, evFork, 0);

    // s2: CSR build (independent)
    k_zero_counts<<<(NN + 255) / 256, 256, 0, s2>>>();
    k_count<<<(EE + 255) / 256, 256, 0, s2>>>(adj);
    k_scanfused<<<nscan, SCAN_B, 0, s2>>>();
    k_scatter<<<(EE + 255) / 256, 256, 0, s2>>>(adj, av);
    cudaEventRecord(evCSR, s2);

    // s0: round weights, then GEMM1 n-blocks {1,2} (the ones spmm needs)
    k_roundw<<<(NW14 + NW24 + 255) / 256, 256>>>((const float4*)w1, (const float4*)w2);
    cudaEventRecord(evW, 0);
    k_gemm_tc<<<dim3(2, mtiles), 256, GEMM_SMEM_BYTES>>>(
        x, F_IN, w1r, F_IN * HH, b1, bufA, bufB + HH, bufB + 2 * HH,
        NN, F_IN, 1, /*nb_off=*/1, /*accum=*/0);

    // s1: GEMM1 n-block 0 (only needed by GEMM2) — overlaps spmm256_1
    cudaStreamWaitEvent(s1, evW, 0);
    k_gemm_tc<<<dim3(1, mtiles), 256, GEMM_SMEM_BYTES, s1>>>(
        x, F_IN, w1r, F_IN * HH, b1, bufA, bufB + HH, bufB + 2 * HH,
        NN, F_IN, 1, 0, 0);

    // s0: stage-1 hops (need CSR)
    cudaStreamWaitEvent(0, evCSR, 0);
    k_spmm256<<<sblocks, 128>>>(bufB + HH, bufA + HH, bufC + 2 * HH);
    cudaEventRecord(evSp1a, 0);
    k_spmm128<<<sblocks, 128>>>(bufC + 2 * HH, bufA + 2 * HH);

    // s1: GEMM2 partial k0 (A = bufA cols 0..127) — overlaps spmm256_1
    k_gemm_tc<<<dim3(3, mtiles), 256, GEMM_SMEM_BYTES, s1>>>(
        bufA, LD3H, w2r, LD3H * HH, (const float*)0,
        bufC, bufD + HH, bufD + 2 * HH, NN, 128, 0, 0, 0);
    // s1: GEMM2 partial k1 (A = bufA cols 128..255, from spmm256_1) — overlaps spmm128_1
    cudaStreamWaitEvent(s1, evSp1a, 0);
    k_gemm_tc<<<dim3(3, mtiles), 256, GEMM_SMEM_BYTES, s1>>>(
        bufA + 128, LD3H, w2r + 128 * 128, LD3H * HH, (const float*)0,
        bufC, bufD + HH, bufD + 2 * HH, NN, 128, 0, 0, 1);
    cudaEventRecord(evS1d, s1);

    // s0: GEMM2 partial k2 (A = bufA cols 256..383, from spmm128_1)
    cudaStreamWaitEvent(0, evS1d, 0);
    k_gemm_tc<<<dim3(3, mtiles), 256, GEMM_SMEM_BYTES>>>(
        bufA + 256, LD3H, w2r + 256 * 128, LD3H * HH, (const float*)0,
        bufC, bufD + HH, bufD + 2 * HH, NN, 128, 0, 0, 1);

    // s0: stage-2 hops
    k_spmm256<<<sblocks, 128>>>(bufD + HH, bufC + HH, bufB + 2 * HH);
    k_spmm128<<<sblocks, 128>>>(bufB + 2 * HH, bufC + 2 * HH);

    // s0: final
    k_final<<<(NN + FROWS - 1) / FROWS, 128>>>(bufC, b2, wf, bf, out);

    (void)in_sizes; (void)n_in; (void)out_size;
}

// round 7
// speedup vs baseline: 1.1967x; 1.1967x over previous
#include <cuda_runtime.h>
#include <cuda_fp16.h>
#include <math.h>
#include <stdint.h>

// Problem constants
#define NN 50000
#define EE 800000
#define F_IN 512
#define HH 128
#define CC 16
#define LD3H 384   // 3*H

// ---------------- device scratch (static, no allocations) ----------------
__device__ int    g_count[NN];
__device__ int    g_rowptr[NN + 1];
__device__ int    g_pos[NN];
__device__ int    g_state[64];
__device__ int    g_col[EE];
__device__ float  g_val[EE];
__device__ float  g_bufA[(size_t)NN * LD3H];
__device__ float  g_bufC[(size_t)NN * LD3H];
__device__ __half g_h16B[(size_t)NN * 256];   // GEMM out blocks 1,2 (fp16, ld 256)
__device__ __half g_h16C[(size_t)NN * 128];   // mid-hop block2 (fp16, ld 128)
__device__ float  g_w1r[3 * F_IN * HH];       // tf32-rounded w1
__device__ float  g_w2r[3 * LD3H * HH];       // tf32-rounded w2

// ---------------- helpers ----------------
__device__ __forceinline__ float f2tf_f(float f) {
    uint32_t u; asm("cvt.rna.tf32.f32 %0, %1;" : "=r"(u) : "f"(f));
    return __uint_as_float(u);
}
__device__ __forceinline__ uint32_t f2tf(float f) {
    uint32_t u; asm("cvt.rna.tf32.f32 %0, %1;" : "=r"(u) : "f"(f)); return u;
}

__device__ __forceinline__ void mma_tf32(float* c, const uint32_t* a, const uint32_t* b) {
    asm volatile(
        "mma.sync.aligned.m16n8k8.row.col.f32.tf32.tf32.f32 "
        "{%0,%1,%2,%3}, {%4,%5,%6,%7}, {%8,%9}, {%0,%1,%2,%3};\n"
        : "+f"(c[0]), "+f"(c[1]), "+f"(c[2]), "+f"(c[3])
        : "r"(a[0]), "r"(a[1]), "r"(a[2]), "r"(a[3]), "r"(b[0]), "r"(b[1]));
}

__device__ __forceinline__ void cpa16(uint32_t dst_smem, const void* src, int valid) {
    asm volatile("cp.async.cg.shared.global [%0], [%1], 16, %2;\n"
                 :: "r"(dst_smem), "l"(src), "r"(valid ? 16 : 0));
}
__device__ __forceinline__ void cpa_commit() { asm volatile("cp.async.commit_group;\n"); }
__device__ __forceinline__ void cpa_wait0()  { asm volatile("cp.async.wait_group 0;\n"); }

// ---------------- weight round to tf32 ----------------
#define NW14  (3 * F_IN * HH / 4)
#define NW24  (3 * LD3H * HH / 4)
__global__ void k_roundw(const float4* __restrict__ w1, const float4* __restrict__ w2)
{
    int i = blockIdx.x * blockDim.x + threadIdx.x;
    if (i < NW14) {
        float4 v = w1[i];
        v.x = f2tf_f(v.x); v.y = f2tf_f(v.y); v.z = f2tf_f(v.z); v.w = f2tf_f(v.w);
        ((float4*)g_w1r)[i] = v;
    } else if (i < NW14 + NW24) {
        int j = i - NW14;
        float4 v = w2[j];
        v.x = f2tf_f(v.x); v.y = f2tf_f(v.y); v.z = f2tf_f(v.z); v.w = f2tf_f(v.w);
        ((float4*)g_w2r)[j] = v;
    }
}

// ---------------- CSR build ----------------
__global__ void k_zero_counts() {
    int i = blockIdx.x * blockDim.x + threadIdx.x;
    if (i < NN) g_count[i] = 0;
    if (i < 64) g_state[i] = -1;
}

__global__ void k_count(const int* __restrict__ idx) {
    int e = blockIdx.x * blockDim.x + threadIdx.x;
    if (e < EE) atomicAdd(&g_count[idx[e]], 1);
}

#define SCAN_B 1024
__global__ void k_scanfused() {
    __shared__ int s[SCAN_B];
    __shared__ int pfx;
    int t = threadIdx.x;
    int b = blockIdx.x;
    int i = b * SCAN_B + t;
    int v = (i < NN) ? g_count[i] : 0;
    s[t] = v;
    __syncthreads();
    #pragma unroll
    for (int o = 1; o < SCAN_B; o <<= 1) {
        int u = (t >= o) ? s[t - o] : 0;
        __syncthreads();
        s[t] += u;
        __syncthreads();
    }
    if (t == 0) {
        int total = s[SCAN_B - 1];
        int p = 0;
        if (b > 0) {
            while ((p = atomicAdd(&g_state[b - 1], 0)) < 0) {}
        }
        pfx = p;
        __threadfence();
        atomicExch(&g_state[b], p + total);
    }
    __syncthreads();
    if (i < NN) {
        int e = pfx + s[t] - v;
        g_rowptr[i] = e;
        g_pos[i] = e;
    }
    if (i == 0) g_rowptr[NN] = EE;
}

__global__ void k_scatter(const int* __restrict__ idx, const float* __restrict__ vals) {
    int e = blockIdx.x * blockDim.x + threadIdx.x;
    if (e < EE) {
        int r = idx[e];
        int p = atomicAdd(&g_pos[r], 1);
        g_col[p] = idx[EE + e];
        g_val[p] = vals[e];
    }
}

// ---------------- tf32 tensor-core GEMM, cp.async double-buffered ----------------
// nb=0 -> C0 fp32 (ld 384); nb=1,2 -> Hout fp16 (ld 256, col offset (nb-1)*128)
#define LDA_S 36
#define LDB_S 136
#define A_BUF_W (128 * LDA_S)
#define B_BUF_W (32 * LDB_S)
#define GEMM_SMEM_BYTES ((2 * A_BUF_W + 2 * B_BUF_W) * 4)

__global__ __launch_bounds__(256, 2)
void k_gemm_tc(const float* __restrict__ A, int lda,
               const float* __restrict__ Bbase, int bstride,
               const float* __restrict__ bias,      // [3*128] or null
               float* __restrict__ C0, __half* __restrict__ Hout,
               int M, int K, int do_relu)
{
    extern __shared__ uint32_t smem[];
    uint32_t* As = smem;
    uint32_t* Bs = smem + 2 * A_BUF_W;

    const int nb = blockIdx.x;
    const float* B = Bbase + (size_t)nb * bstride;
    const float* bi = bias ? (bias + nb * 128) : (const float*)0;

    const int m0   = blockIdx.y * 128;
    const int tid  = threadIdx.x;
    const int lane = tid & 31;
    const int wid  = tid >> 5;
    const int wm0  = (wid & 1) * 64;
    const int wn0  = (wid >> 1) * 32;
    const int gp   = lane >> 2;
    const int tg   = lane & 3;

    float acc[4][4][4];
    #pragma unroll
    for (int i = 0; i < 4; i++)
        #pragma unroll
        for (int j = 0; j < 4; j++)
            #pragma unroll
            for (int q = 0; q < 4; q++) acc[i][j][q] = 0.f;

    const int nk = K >> 5;

    auto stage = [&](int kt, int buf) {
        const int k0 = kt << 5;
        uint32_t abase = (uint32_t)__cvta_generic_to_shared(As + buf * A_BUF_W);
        uint32_t bbase = (uint32_t)__cvta_generic_to_shared(Bs + buf * B_BUF_W);
        #pragma unroll
        for (int s = 0; s < 4; s++) {
            int idx = s * 256 + tid;
            int r = idx >> 3;
            int c = (idx & 7) * 4;
            int gr = m0 + r;
            int ok = gr < M;
            int srow = ok ? gr : (M - 1);
            cpa16(abase + (r * LDA_S + c) * 4, A + (size_t)srow * lda + k0 + c, ok);
        }
        #pragma unroll
        for (int s = 0; s < 4; s++) {
            int idx = s * 256 + tid;
            int r = idx >> 5;
            int c = (idx & 31) * 4;
            cpa16(bbase + (r * LDB_S + c) * 4, B + (size_t)(k0 + r) * 128 + c, 1);
        }
        cpa_commit();
    };

    stage(0, 0);

    for (int kt = 0; kt < nk; kt++) {
        cpa_wait0();
        __syncthreads();
        if (kt + 1 < nk) stage(kt + 1, (kt + 1) & 1);

        const uint32_t* Ab = As + (kt & 1) * A_BUF_W;
        const uint32_t* Bb = Bs + (kt & 1) * B_BUF_W;

        #pragma unroll
        for (int ks = 0; ks < 4; ks++) {
            uint32_t af[4][4], bf[4][2];
            const int kk = ks * 8 + tg;
            #pragma unroll
            for (int i = 0; i < 4; i++) {
                int r = wm0 + i * 16 + gp;
                af[i][0] = f2tf(__uint_as_float(Ab[r * LDA_S + kk]));
                af[i][1] = f2tf(__uint_as_float(Ab[(r + 8) * LDA_S + kk]));
                af[i][2] = f2tf(__uint_as_float(Ab[r * LDA_S + kk + 4]));
                af[i][3] = f2tf(__uint_as_float(Ab[(r + 8) * LDA_S + kk + 4]));
            }
            #pragma unroll
            for (int j = 0; j < 4; j++) {
                int n = wn0 + j * 8 + gp;
                bf[j][0] = Bb[kk * LDB_S + n];
                bf[j][1] = Bb[(kk + 4) * LDB_S + n];
            }
            #pragma unroll
            for (int i = 0; i < 4; i++)
                #pragma unroll
                for (int j = 0; j < 4; j++)
                    mma_tf32(acc[i][j], af[i], bf[j]);
        }
        __syncthreads();
    }

    #pragma unroll
    for (int i = 0; i < 4; i++) {
        #pragma unroll
        for (int rr = 0; rr < 2; rr++) {
            int row = m0 + wm0 + i * 16 + gp + rr * 8;
            if (row >= M) continue;
            #pragma unroll
            for (int j = 0; j < 4; j++) {
                int col = wn0 + j * 8 + 2 * tg;
                float2 v;
                v.x = acc[i][j][rr * 2 + 0];
                v.y = acc[i][j][rr * 2 + 1];
                if (bi) { v.x += bi[col]; v.y += bi[col + 1]; }
                if (do_relu) { v.x = fmaxf(v.x, 0.f); v.y = fmaxf(v.y, 0.f); }
                if (nb == 0) {
                    *(float2*)(C0 + (size_t)row * LD3H + col) = v;
                } else {
                    __half2 h = __floats2half2_rn(v.x, v.y);
                    *(__half2*)(Hout + (size_t)row * 256 + (nb - 1) * 128 + col) = h;
                }
            }
        }
    }
}

// ---------------- SpMM (CSR gather, fp16 sources) ----------------
// 256-wide: lane reads 8 halves (16B). lanes 0-15 -> block1 (fp32 out),
// lanes 16-31 -> block2 (fp16 out for next hop).
__global__ void k_spmm256h(const __half* __restrict__ src,
                           float* __restrict__ dstA, __half* __restrict__ dstH)
{
    int warp = (blockIdx.x * blockDim.x + threadIdx.x) >> 5;
    int lane = threadIdx.x & 31;
    if (warp >= NN) return;
    int s = g_rowptr[warp];
    int e = g_rowptr[warp + 1];
    float a[8];
    #pragma unroll
    for (int q = 0; q < 8; q++) a[q] = 0.f;
    int p = s;
    for (; p + 1 < e; p += 2) {
        int   c0 = g_col[p],   c1 = g_col[p + 1];
        float v0 = g_val[p],   v1 = g_val[p + 1];
        uint4 q0 = *(const uint4*)(src + (size_t)c0 * 256 + lane * 8);
        uint4 q1 = *(const uint4*)(src + (size_t)c1 * 256 + lane * 8);
        const __half2* h0 = (const __half2*)&q0;
        const __half2* h1 = (const __half2*)&q1;
        #pragma unroll
        for (int k = 0; k < 4; k++) {
            float2 f0 = __half22float2(h0[k]);
            float2 f1 = __half22float2(h1[k]);
            a[2 * k]     = fmaf(v0, f0.x, a[2 * k]);
            a[2 * k + 1] = fmaf(v0, f0.y, a[2 * k + 1]);
            a[2 * k]     = fmaf(v1, f1.x, a[2 * k]);
            a[2 * k + 1] = fmaf(v1, f1.y, a[2 * k + 1]);
        }
    }
    if (p < e) {
        int c0 = g_col[p];
        float v0 = g_val[p];
        uint4 q0 = *(const uint4*)(src + (size_t)c0 * 256 + lane * 8);
        const __half2* h0 = (const __half2*)&q0;
        #pragma unroll
        for (int k = 0; k < 4; k++) {
            float2 f0 = __half22float2(h0[k]);
            a[2 * k]     = fmaf(v0, f0.x, a[2 * k]);
            a[2 * k + 1] = fmaf(v0, f0.y, a[2 * k + 1]);
        }
    }
    if (lane < 16) {
        // block1, cols = lane*8 .. lane*8+7 -> fp32, ld 384
        float* d = dstA + (size_t)warp * LD3H + lane * 8;
        *(float4*)d       = make_float4(a[0], a[1], a[2], a[3]);
        *(float4*)(d + 4) = make_float4(a[4], a[5], a[6], a[7]);
    } else {
        // block2, cols = (lane-16)*8 -> fp16, ld 128
        __half2 h[4];
        #pragma unroll
        for (int k = 0; k < 4; k++) h[k] = __floats2half2_rn(a[2 * k], a[2 * k + 1]);
        *(uint4*)(dstH + (size_t)warp * 128 + (lane - 16) * 8) = *(uint4*)h;
    }
}

// 128-wide fp16 source -> fp32 dst (ld 384): lane reads 4 halves (8B)
__global__ void k_spmm128h(const __half* __restrict__ src, float* __restrict__ dst)
{
    int warp = (blockIdx.x * blockDim.x + threadIdx.x) >> 5;
    int lane = threadIdx.x & 31;
    if (warp >= NN) return;
    int s = g_rowptr[warp];
    int e = g_rowptr[warp + 1];
    float a[4];
    #pragma unroll
    for (int q = 0; q < 4; q++) a[q] = 0.f;
    int p = s;
    for (; p + 1 < e; p += 2) {
        int   c0 = g_col[p],   c1 = g_col[p + 1];
        float v0 = g_val[p],   v1 = g_val[p + 1];
        uint2 q0 = *(const uint2*)(src + (size_t)c0 * 128 + lane * 4);
        uint2 q1 = *(const uint2*)(src + (size_t)c1 * 128 + lane * 4);
        const __half2* h0 = (const __half2*)&q0;
        const __half2* h1 = (const __half2*)&q1;
        #pragma unroll
        for (int k = 0; k < 2; k++) {
            float2 f0 = __half22float2(h0[k]);
            float2 f1 = __half22float2(h1[k]);
            a[2 * k]     = fmaf(v0, f0.x, a[2 * k]);
            a[2 * k + 1] = fmaf(v0, f0.y, a[2 * k + 1]);
            a[2 * k]     = fmaf(v1, f1.x, a[2 * k]);
            a[2 * k + 1] = fmaf(v1, f1.y, a[2 * k + 1]);
        }
    }
    if (p < e) {
        int c0 = g_col[p];
        float v0 = g_val[p];
        uint2 q0 = *(const uint2*)(src + (size_t)c0 * 128 + lane * 4);
        const __half2* h0 = (const __half2*)&q0;
        #pragma unroll
        for (int k = 0; k < 2; k++) {
            float2 f0 = __half22float2(h0[k]);
            a[2 * k]     = fmaf(v0, f0.x, a[2 * k]);
            a[2 * k + 1] = fmaf(v0, f0.y, a[2 * k + 1]);
        }
    }
    *(float4*)(dst + (size_t)warp * LD3H + lane * 4) = make_float4(a[0], a[1], a[2], a[3]);
}

// ---------------- final ----------------
#define FROWS 8
__global__ __launch_bounds__(128)
void k_final(const float* __restrict__ g,
             const float* __restrict__ b2,
             const float* __restrict__ wf,
             const float* __restrict__ bfv,
             float* __restrict__ out)
{
    __shared__ float wfs[LD3H * CC];
    __shared__ float gs[FROWS][LD3H];
    int tid = threadIdx.x;
    for (int i = tid; i < LD3H * CC; i += 128) wfs[i] = wf[i];
    int row0 = blockIdx.x * FROWS;
    for (int i = tid; i < FROWS * LD3H; i += 128) {
        int r = i / LD3H, k = i % LD3H;
        int gr = row0 + r;
        gs[r][k] = (gr < NN) ? g[(size_t)gr * LD3H + k] + b2[k] : 0.f;
    }
    __syncthreads();

    int r = tid >> 4;
    int c = tid & 15;
    float acc = bfv[c];
    #pragma unroll 8
    for (int k = 0; k < LD3H; k++) acc = fmaf(gs[r][k], wfs[k * CC + c], acc);

    float m = acc;
    #pragma unroll
    for (int o = 8; o >= 1; o >>= 1) m = fmaxf(m, __shfl_xor_sync(0xffffffffu, m, o, 16));
    float ex = __expf(acc - m);
    float s = ex;
    #pragma unroll
    for (int o = 8; o >= 1; o >>= 1) s += __shfl_xor_sync(0xffffffffu, s, o, 16);
    int gr = row0 + r;
    if (gr < NN) out[gr * CC + c] = acc - m - logf(s);
}

// ---------------- launch ----------------
extern "C" void kernel_launch(void* const* d_in, const int* in_sizes, int n_in,
                              void* d_out, int out_size)
{
    const float* x   = (const float*)d_in[0];
    const int*   adj = (const int*)d_in[1];
    const float* av  = (const float*)d_in[2];
    const float* w1  = (const float*)d_in[3];
    const float* b1  = (const float*)d_in[4];
    const float* w2  = (const float*)d_in[5];
    const float* b2  = (const float*)d_in[6];
    const float* wf  = (const float*)d_in[7];
    const float* bf  = (const float*)d_in[8];
    float* out = (float*)d_out;

    float *bufA, *bufC, *w1r, *w2r;
    __half *h16B, *h16C;
    cudaGetSymbolAddress((void**)&bufA, g_bufA);
    cudaGetSymbolAddress((void**)&bufC, g_bufC);
    cudaGetSymbolAddress((void**)&h16B, g_h16B);
    cudaGetSymbolAddress((void**)&h16C, g_h16C);
    cudaGetSymbolAddress((void**)&w1r,  g_w1r);
    cudaGetSymbolAddress((void**)&w2r,  g_w2r);

    cudaFuncSetAttribute(k_gemm_tc, cudaFuncAttributeMaxDynamicSharedMemorySize,
                         GEMM_SMEM_BYTES);

    static cudaStream_t s2 = 0;
    static cudaEvent_t evFork = 0, evCSR = 0;
    if (!s2) {
        cudaStreamCreateWithFlags(&s2, cudaStreamNonBlocking);
        cudaEventCreateWithFlags(&evFork, cudaEventDisableTiming);
        cudaEventCreateWithFlags(&evCSR,  cudaEventDisableTiming);
    }

    const int nscan = (NN + SCAN_B - 1) / SCAN_B;   // 49
    const int mtiles = (NN + 127) / 128;            // 391
    const int sblocks = (NN + 3) / 4;

    // ---- fork: CSR on s2 ----
    cudaEventRecord(evFork, 0);
    cudaStreamWaitEvent(s2, evFork, 0);
    k_zero_counts<<<(NN + 255) / 256, 256, 0, s2>>>();
    k_count<<<(EE + 255) / 256, 256, 0, s2>>>(adj);
    k_scanfused<<<nscan, SCAN_B, 0, s2>>>();
    k_scatter<<<(EE + 255) / 256, 256, 0, s2>>>(adj, av);
    cudaEventRecord(evCSR, s2);

    // s0: round weights + GEMM1 (block0 -> bufA fp32; blocks1,2 -> h16B fp16)
    k_roundw<<<(NW14 + NW24 + 255) / 256, 256>>>((const float4*)w1, (const float4*)w2);
    k_gemm_tc<<<dim3(3, mtiles), 256, GEMM_SMEM_BYTES>>>(
        x, F_IN, w1r, F_IN * HH, b1, bufA, h16B, NN, F_IN, 1);

    // join: spmm needs CSR
    cudaStreamWaitEvent(0, evCSR, 0);

    // stage-1 hops
    k_spmm256h<<<sblocks, 128>>>(h16B, bufA + HH, h16C);
    k_spmm128h<<<sblocks, 128>>>(h16C, bufA + 2 * HH);

    // GEMM2 (block0 -> bufC fp32; blocks1,2 -> h16B fp16), bias deferred
    k_gemm_tc<<<dim3(3, mtiles), 256, GEMM_SMEM_BYTES>>>(
        bufA, LD3H, w2r, LD3H * HH, (const float*)0, bufC, h16B, NN, LD3H, 0);

    // stage-2 hops
    k_spmm256h<<<sblocks, 128>>>(h16B, bufC + HH, h16C);
    k_spmm128h<<<sblocks, 128>>>(h16C, bufC + 2 * HH);

    // final
    k_final<<<(NN + FROWS - 1) / FROWS, 128>>>(bufC, b2, wf, bf, out);

    (void)in_sizes; (void)n_in; (void)out_size;
}

// round 8
// speedup vs baseline: 1.3864x; 1.1585x over previous
#include <cuda_runtime.h>
#include <cuda_fp16.h>
#include <math.h>
#include <stdint.h>

// Problem constants
#define NN 50000
#define EE 800000
#define F_IN 512
#define HH 128
#define CC 16
#define LD3H 384   // 3*H

// ---------------- device scratch (static, no allocations) ----------------
__device__ int    g_count[NN];
__device__ int    g_rowptr[NN + 1];
__device__ int    g_pos[NN];
__device__ int    g_state[64];
__device__ int    g_col[EE];
__device__ float  g_val[EE];
__device__ float  g_bufC[(size_t)NN * LD3H];   // stage-2 result (fp32, for final)
__device__ __half g_xh[(size_t)NN * F_IN];     // x in fp16
__device__ __half g_a1h[(size_t)NN * LD3H];    // a1 in fp16 (ld 384)
__device__ __half g_h16B[(size_t)NN * 256];    // GEMM out blocks 1,2 (fp16, ld 256)
__device__ __half g_h16C[(size_t)NN * 128];    // mid-hop block2 (fp16, ld 128)
__device__ __half g_w1h[3 * 128 * F_IN];       // w1^T fp16 [3][128 n][512 k]
__device__ __half g_w2h[3 * 128 * LD3H];       // w2^T fp16 [3][128 n][384 k]

// ---------------- helpers ----------------
__device__ __forceinline__ void mma_f16(float* c, const uint32_t* a, const uint32_t* b) {
    asm volatile(
        "mma.sync.aligned.m16n8k16.row.col.f32.f16.f16.f32 "
        "{%0,%1,%2,%3}, {%4,%5,%6,%7}, {%8,%9}, {%0,%1,%2,%3};\n"
        : "+f"(c[0]), "+f"(c[1]), "+f"(c[2]), "+f"(c[3])
        : "r"(a[0]), "r"(a[1]), "r"(a[2]), "r"(a[3]), "r"(b[0]), "r"(b[1]));
}

__device__ __forceinline__ void cpa16(uint32_t dst_smem, const void* src, int valid) {
    asm volatile("cp.async.cg.shared.global [%0], [%1], 16, %2;\n"
                 :: "r"(dst_smem), "l"(src), "r"(valid ? 16 : 0));
}
__device__ __forceinline__ void cpa_commit() { asm volatile("cp.async.commit_group;\n"); }
__device__ __forceinline__ void cpa_wait0()  { asm volatile("cp.async.wait_group 0;\n"); }

// ---------------- prep: x -> fp16 ----------------
#define NXE ((size_t)NN * F_IN)   // 25,600,000
__global__ void k_xhalf(const float4* __restrict__ x)
{
    size_t i = (size_t)blockIdx.x * blockDim.x + threadIdx.x;   // 8 floats each
    if (i * 8 >= NXE) return;
    float4 v0 = x[i * 2];
    float4 v1 = x[i * 2 + 1];
    __half2 h[4];
    h[0] = __floats2half2_rn(v0.x, v0.y);
    h[1] = __floats2half2_rn(v0.z, v0.w);
    h[2] = __floats2half2_rn(v1.x, v1.y);
    h[3] = __floats2half2_rn(v1.z, v1.w);
    *(uint4*)(g_xh + i * 8) = *(uint4*)h;
}

// ---------------- prep: W [3][K][128] -> W^T fp16 [3][128][K] ----------------
__global__ void k_wth(const float* __restrict__ W, __half* __restrict__ WT, int K)
{
    __shared__ float t[32][33];
    int z  = blockIdx.z;
    int k0 = blockIdx.x * 32;
    int n0 = blockIdx.y * 32;
    int tx = threadIdx.x, ty = threadIdx.y;  // 32 x 8
    #pragma unroll
    for (int i = 0; i < 4; i++) {
        int k = k0 + ty + i * 8;
        t[ty + i * 8][tx] = W[(size_t)z * K * 128 + (size_t)k * 128 + n0 + tx];
    }
    __syncthreads();
    #pragma unroll
    for (int i = 0; i < 4; i++) {
        int n = n0 + ty + i * 8;
        WT[(size_t)z * 128 * K + (size_t)n * K + k0 + tx] = __float2half_rn(t[tx][ty + i * 8]);
    }
}

// ---------------- CSR build ----------------
__global__ void k_zero_counts() {
    int i = blockIdx.x * blockDim.x + threadIdx.x;
    if (i < NN) g_count[i] = 0;
    if (i < 64) g_state[i] = -1;
}

__global__ void k_count(const int* __restrict__ idx) {
    int e = blockIdx.x * blockDim.x + threadIdx.x;
    if (e < EE) atomicAdd(&g_count[idx[e]], 1);
}

#define SCAN_B 1024
__global__ void k_scanfused() {
    __shared__ int s[SCAN_B];
    __shared__ int pfx;
    int t = threadIdx.x;
    int b = blockIdx.x;
    int i = b * SCAN_B + t;
    int v = (i < NN) ? g_count[i] : 0;
    s[t] = v;
    __syncthreads();
    #pragma unroll
    for (int o = 1; o < SCAN_B; o <<= 1) {
        int u = (t >= o) ? s[t - o] : 0;
        __syncthreads();
        s[t] += u;
        __syncthreads();
    }
    if (t == 0) {
        int total = s[SCAN_B - 1];
        int p = 0;
        if (b > 0) {
            while ((p = atomicAdd(&g_state[b - 1], 0)) < 0) {}
        }
        pfx = p;
        __threadfence();
        atomicExch(&g_state[b], p + total);
    }
    __syncthreads();
    if (i < NN) {
        int e = pfx + s[t] - v;
        g_rowptr[i] = e;
        g_pos[i] = e;
    }
    if (i == 0) g_rowptr[NN] = EE;
}

__global__ void k_scatter(const int* __restrict__ idx, const float* __restrict__ vals) {
    int e = blockIdx.x * blockDim.x + threadIdx.x;
    if (e < EE) {
        int r = idx[e];
        int p = atomicAdd(&g_pos[r], 1);
        g_col[p] = idx[EE + e];
        g_val[p] = vals[e];
    }
}

// ---------------- fp16 tensor-core GEMM (m16n8k16), cp.async double-buffered ----------------
// Block tile 128x128, BK=32, 8 warps, warp tile 64x32.
// A [M,K] fp16 row-major; Bt [3][128 n][K] fp16 (transposed weights).
// nb=0: out -> C0f fp32 (ld384) if non-null, else C0h fp16 (ld384).
// nb=1,2: out -> Hout fp16 (ld 256, col offset (nb-1)*128).
#define AH_LD 40                       // halves per row (80B, conflict-free)
#define AH_BUF (128 * AH_LD)           // halves per buffer
#define GH_SMEM_BYTES (4 * AH_BUF * 2) // 2 bufs x (A+B), in bytes = 40960

__global__ __launch_bounds__(256, 2)
void k_gemm_h(const __half* __restrict__ A, int lda,
              const __half* __restrict__ Bt,
              const float* __restrict__ bias,
              float* __restrict__ C0f, __half* __restrict__ C0h,
              __half* __restrict__ Hout,
              int M, int K, int do_relu)
{
    extern __shared__ __half smh[];
    __half* As = smh;                       // [2][128][AH_LD]
    __half* Bs = smh + 2 * AH_BUF;          // [2][128][AH_LD]

    const int nb = blockIdx.x;
    const __half* B = Bt + (size_t)nb * 128 * K;
    const float* bi = bias ? (bias + nb * 128) : (const float*)0;

    const int m0   = blockIdx.y * 128;
    const int tid  = threadIdx.x;
    const int lane = tid & 31;
    const int wid  = tid >> 5;
    const int wm0  = (wid & 1) * 64;
    const int wn0  = (wid >> 1) * 32;
    const int gp   = lane >> 2;
    const int tg   = lane & 3;

    float acc[4][4][4];
    #pragma unroll
    for (int i = 0; i < 4; i++)
        #pragma unroll
        for (int j = 0; j < 4; j++)
            #pragma unroll
            for (int q = 0; q < 4; q++) acc[i][j][q] = 0.f;

    const int nk = K >> 5;

    auto stage = [&](int kt, int buf) {
        const int k0 = kt << 5;
        uint32_t abase = (uint32_t)__cvta_generic_to_shared(As + buf * AH_BUF);
        uint32_t bbase = (uint32_t)__cvta_generic_to_shared(Bs + buf * AH_BUF);
        #pragma unroll
        for (int s = 0; s < 2; s++) {
            int idx = s * 256 + tid;          // 0..511
            int r = idx >> 2;                 // 0..127
            int c = (idx & 3) * 8;            // halves
            int gr = m0 + r;
            int ok = gr < M;
            int sr = ok ? gr : (M - 1);
            cpa16(abase + (r * AH_LD + c) * 2, A + (size_t)sr * lda + k0 + c, ok);
        }
        #pragma unroll
        for (int s = 0; s < 2; s++) {
            int idx = s * 256 + tid;
            int r = idx >> 2;                 // n row 0..127
            int c = (idx & 3) * 8;
            cpa16(bbase + (r * AH_LD + c) * 2, B + (size_t)r * K + k0 + c, 1);
        }
        cpa_commit();
    };

    stage(0, 0);

    for (int kt = 0; kt < nk; kt++) {
        cpa_wait0();
        __syncthreads();
        if (kt + 1 < nk) stage(kt + 1, (kt + 1) & 1);

        const __half* Ab = As + (kt & 1) * AH_BUF;
        const __half* Bb = Bs + (kt & 1) * AH_BUF;

        #pragma unroll
        for (int ks = 0; ks < 2; ks++) {
            const int kk = ks * 16 + 2 * tg;
            uint32_t af[4][4], bf[4][2];
            #pragma unroll
            for (int i = 0; i < 4; i++) {
                int r = wm0 + i * 16 + gp;
                af[i][0] = *(const uint32_t*)&Ab[r * AH_LD + kk];
                af[i][1] = *(const uint32_t*)&Ab[(r + 8) * AH_LD + kk];
                af[i][2] = *(const uint32_t*)&Ab[r * AH_LD + kk + 8];
                af[i][3] = *(const uint32_t*)&Ab[(r + 8) * AH_LD + kk + 8];
            }
            #pragma unroll
            for (int j = 0; j < 4; j++) {
                int n = wn0 + j * 8 + gp;
                bf[j][0] = *(const uint32_t*)&Bb[n * AH_LD + kk];
                bf[j][1] = *(const uint32_t*)&Bb[n * AH_LD + kk + 8];
            }
            #pragma unroll
            for (int i = 0; i < 4; i++)
                #pragma unroll
                for (int j = 0; j < 4; j++)
                    mma_f16(acc[i][j], af[i], bf[j]);
        }
        __syncthreads();
    }

    #pragma unroll
    for (int i = 0; i < 4; i++) {
        #pragma unroll
        for (int rr = 0; rr < 2; rr++) {
            int row = m0 + wm0 + i * 16 + gp + rr * 8;
            if (row >= M) continue;
            #pragma unroll
            for (int j = 0; j < 4; j++) {
                int col = wn0 + j * 8 + 2 * tg;
                float2 v;
                v.x = acc[i][j][rr * 2 + 0];
                v.y = acc[i][j][rr * 2 + 1];
                if (bi) { v.x += bi[col]; v.y += bi[col + 1]; }
                if (do_relu) { v.x = fmaxf(v.x, 0.f); v.y = fmaxf(v.y, 0.f); }
                if (nb == 0) {
                    if (C0f) {
                        *(float2*)(C0f + (size_t)row * LD3H + col) = v;
                    } else {
                        *(__half2*)(C0h + (size_t)row * LD3H + col) =
                            __floats2half2_rn(v.x, v.y);
                    }
                } else {
                    *(__half2*)(Hout + (size_t)row * 256 + (nb - 1) * 128 + col) =
                        __floats2half2_rn(v.x, v.y);
                }
            }
        }
    }
}

// ---------------- SpMM (CSR gather, fp16 sources) ----------------
// 256-wide: lane reads 8 halves. lanes 0-15 -> block1, lanes 16-31 -> block2 (->dstH2).
// OUT16: block1 written fp16 to dstH1 (ld 384) if 1, else fp32 to dstF (ld 384).
template<int OUT16>
__global__ void k_spmm256t(const __half* __restrict__ src,
                           float* __restrict__ dstF, __half* __restrict__ dstH1,
                           __half* __restrict__ dstH2)
{
    int warp = (blockIdx.x * blockDim.x + threadIdx.x) >> 5;
    int lane = threadIdx.x & 31;
    if (warp >= NN) return;
    int s = g_rowptr[warp];
    int e = g_rowptr[warp + 1];
    float a[8];
    #pragma unroll
    for (int q = 0; q < 8; q++) a[q] = 0.f;
    int p = s;
    for (; p + 1 < e; p += 2) {
        int   c0 = g_col[p],   c1 = g_col[p + 1];
        float v0 = g_val[p],   v1 = g_val[p + 1];
        uint4 q0 = *(const uint4*)(src + (size_t)c0 * 256 + lane * 8);
        uint4 q1 = *(const uint4*)(src + (size_t)c1 * 256 + lane * 8);
        const __half2* h0 = (const __half2*)&q0;
        const __half2* h1 = (const __half2*)&q1;
        #pragma unroll
        for (int k = 0; k < 4; k++) {
            float2 f0 = __half22float2(h0[k]);
            float2 f1 = __half22float2(h1[k]);
            a[2 * k]     = fmaf(v0, f0.x, a[2 * k]);
            a[2 * k + 1] = fmaf(v0, f0.y, a[2 * k + 1]);
            a[2 * k]     = fmaf(v1, f1.x, a[2 * k]);
            a[2 * k + 1] = fmaf(v1, f1.y, a[2 * k + 1]);
        }
    }
    if (p < e) {
        int c0 = g_col[p];
        float v0 = g_val[p];
        uint4 q0 = *(const uint4*)(src + (size_t)c0 * 256 + lane * 8);
        const __half2* h0 = (const __half2*)&q0;
        #pragma unroll
        for (int k = 0; k < 4; k++) {
            float2 f0 = __half22float2(h0[k]);
            a[2 * k]     = fmaf(v0, f0.x, a[2 * k]);
            a[2 * k + 1] = fmaf(v0, f0.y, a[2 * k + 1]);
        }
    }
    if (lane < 16) {
        if (OUT16) {
            __half2 h[4];
            #pragma unroll
            for (int k = 0; k < 4; k++) h[k] = __floats2half2_rn(a[2 * k], a[2 * k + 1]);
            *(uint4*)(dstH1 + (size_t)warp * LD3H + lane * 8) = *(uint4*)h;
        } else {
            float* d = dstF + (size_t)warp * LD3H + lane * 8;
            *(float4*)d       = make_float4(a[0], a[1], a[2], a[3]);
            *(float4*)(d + 4) = make_float4(a[4], a[5], a[6], a[7]);
        }
    } else {
        __half2 h[4];
        #pragma unroll
        for (int k = 0; k < 4; k++) h[k] = __floats2half2_rn(a[2 * k], a[2 * k + 1]);
        *(uint4*)(dstH2 + (size_t)warp * 128 + (lane - 16) * 8) = *(uint4*)h;
    }
}

// 128-wide fp16 source; OUT16 -> dstH (ld 384) else dstF (ld 384)
template<int OUT16>
__global__ void k_spmm128t(const __half* __restrict__ src,
                           float* __restrict__ dstF, __half* __restrict__ dstH)
{
    int warp = (blockIdx.x * blockDim.x + threadIdx.x) >> 5;
    int lane = threadIdx.x & 31;
    if (warp >= NN) return;
    int s = g_rowptr[warp];
    int e = g_rowptr[warp + 1];
    float a[4];
    #pragma unroll
    for (int q = 0; q < 4; q++) a[q] = 0.f;
    int p = s;
    for (; p + 1 < e; p += 2) {
        int   c0 = g_col[p],   c1 = g_col[p + 1];
        float v0 = g_val[p],   v1 = g_val[p + 1];
        uint2 q0 = *(const uint2*)(src + (size_t)c0 * 128 + lane * 4);
        uint2 q1 = *(const uint2*)(src + (size_t)c1 * 128 + lane * 4);
        const __half2* h0 = (const __half2*)&q0;
        const __half2* h1 = (const __half2*)&q1;
        #pragma unroll
        for (int k = 0; k < 2; k++) {
            float2 f0 = __half22float2(h0[k]);
            float2 f1 = __half22float2(h1[k]);
            a[2 * k]     = fmaf(v0, f0.x, a[2 * k]);
            a[2 * k + 1] = fmaf(v0, f0.y, a[2 * k + 1]);
            a[2 * k]     = fmaf(v1, f1.x, a[2 * k]);
            a[2 * k + 1] = fmaf(v1, f1.y, a[2 * k + 1]);
        }
    }
    if (p < e) {
        int c0 = g_col[p];
        float v0 = g_val[p];
        uint2 q0 = *(const uint2*)(src + (size_t)c0 * 128 + lane * 4);
        const __half2* h0 = (const __half2*)&q0;
        #pragma unroll
        for (int k = 0; k < 2; k++) {
            float2 f0 = __half22float2(h0[k]);
            a[2 * k]     = fmaf(v0, f0.x, a[2 * k]);
            a[2 * k + 1] = fmaf(v0, f0.y, a[2 * k + 1]);
        }
    }
    if (OUT16) {
        __half2 h[2];
        h[0] = __floats2half2_rn(a[0], a[1]);
        h[1] = __floats2half2_rn(a[2], a[3]);
        *(uint2*)(dstH + (size_t)warp * LD3H + lane * 4) = *(uint2*)h;
    } else {
        *(float4*)(dstF + (size_t)warp * LD3H + lane * 4) =
            make_float4(a[0], a[1], a[2], a[3]);
    }
}

// ---------------- final ----------------
#define FROWS 8
__global__ __launch_bounds__(128)
void k_final(const float* __restrict__ g,
             const float* __restrict__ b2,
             const float* __restrict__ wf,
             const float* __restrict__ bfv,
             float* __restrict__ out)
{
    __shared__ float wfs[LD3H * CC];
    __shared__ float gs[FROWS][LD3H];
    int tid = threadIdx.x;
    for (int i = tid; i < LD3H * CC; i += 128) wfs[i] = wf[i];
    int row0 = blockIdx.x * FROWS;
    for (int i = tid; i < FROWS * LD3H; i += 128) {
        int r = i / LD3H, k = i % LD3H;
        int gr = row0 + r;
        gs[r][k] = (gr < NN) ? g[(size_t)gr * LD3H + k] + b2[k] : 0.f;
    }
    __syncthreads();

    int r = tid >> 4;
    int c = tid & 15;
    float acc = bfv[c];
    #pragma unroll 8
    for (int k = 0; k < LD3H; k++) acc = fmaf(gs[r][k], wfs[k * CC + c], acc);

    float m = acc;
    #pragma unroll
    for (int o = 8; o >= 1; o >>= 1) m = fmaxf(m, __shfl_xor_sync(0xffffffffu, m, o, 16));
    float ex = __expf(acc - m);
    float s = ex;
    #pragma unroll
    for (int o = 8; o >= 1; o >>= 1) s += __shfl_xor_sync(0xffffffffu, s, o, 16);
    int gr = row0 + r;
    if (gr < NN) out[gr * CC + c] = acc - m - logf(s);
}

// ---------------- launch ----------------
extern "C" void kernel_launch(void* const* d_in, const int* in_sizes, int n_in,
                              void* d_out, int out_size)
{
    const float* x   = (const float*)d_in[0];
    const int*   adj = (const int*)d_in[1];
    const float* av  = (const float*)d_in[2];
    const float* w1  = (const float*)d_in[3];
    const float* b1  = (const float*)d_in[4];
    const float* w2  = (const float*)d_in[5];
    const float* b2  = (const float*)d_in[6];
    const float* wf  = (const float*)d_in[7];
    const float* bf  = (const float*)d_in[8];
    float* out = (float*)d_out;

    float *bufC;
    __half *xh, *a1h, *h16B, *h16C, *w1h, *w2h;
    cudaGetSymbolAddress((void**)&bufC, g_bufC);
    cudaGetSymbolAddress((void**)&xh,   g_xh);
    cudaGetSymbolAddress((void**)&a1h,  g_a1h);
    cudaGetSymbolAddress((void**)&h16B, g_h16B);
    cudaGetSymbolAddress((void**)&h16C, g_h16C);
    cudaGetSymbolAddress((void**)&w1h,  g_w1h);
    cudaGetSymbolAddress((void**)&w2h,  g_w2h);

    cudaFuncSetAttribute(k_gemm_h, cudaFuncAttributeMaxDynamicSharedMemorySize,
                         GH_SMEM_BYTES);

    static cudaStream_t s2 = 0;
    static cudaEvent_t evFork = 0, evCSR = 0;
    if (!s2) {
        cudaStreamCreateWithFlags(&s2, cudaStreamNonBlocking);
        cudaEventCreateWithFlags(&evFork, cudaEventDisableTiming);
        cudaEventCreateWithFlags(&evCSR,  cudaEventDisableTiming);
    }

    const int nscan = (NN + SCAN_B - 1) / SCAN_B;   // 49
    const int mtiles = (NN + 127) / 128;            // 391
    const int sblocks = (NN + 3) / 4;

    // ---- fork: CSR on s2 ----
    cudaEventRecord(evFork, 0);
    cudaStreamWaitEvent(s2, evFork, 0);
    k_zero_counts<<<(NN + 255) / 256, 256, 0, s2>>>();
    k_count<<<(EE + 255) / 256, 256, 0, s2>>>(adj);
    k_scanfused<<<nscan, SCAN_B, 0, s2>>>();
    k_scatter<<<(EE + 255) / 256, 256, 0, s2>>>(adj, av);
    cudaEventRecord(evCSR, s2);

    // s0: prep (x->fp16, weights->fp16 transposed)
    k_xhalf<<<(unsigned)((NXE / 8 + 255) / 256), 256>>>((const float4*)x);
    k_wth<<<dim3(F_IN / 32, 4, 3), dim3(32, 8)>>>(w1, w1h, F_IN);
    k_wth<<<dim3(LD3H / 32, 4, 3), dim3(32, 8)>>>(w2, w2h, LD3H);

    // GEMM1: block0 -> a1h fp16; blocks 1,2 -> h16B fp16
    k_gemm_h<<<dim3(3, mtiles), 256, GH_SMEM_BYTES>>>(
        xh, F_IN, w1h, b1, (float*)0, a1h, h16B, NN, F_IN, 1);

    // join: spmm needs CSR
    cudaStreamWaitEvent(0, evCSR, 0);

    // stage-1 hops (all fp16 out)
    k_spmm256t<1><<<sblocks, 128>>>(h16B, (float*)0, a1h + HH, h16C);
    k_spmm128t<1><<<sblocks, 128>>>(h16C, (float*)0, a1h + 2 * HH);

    // GEMM2: block0 -> bufC fp32; blocks 1,2 -> h16B fp16 (bias deferred)
    k_gemm_h<<<dim3(3, mtiles), 256, GH_SMEM_BYTES>>>(
        a1h, LD3H, w2h, (const float*)0, bufC, (__half*)0, h16B, NN, LD3H, 0);

    // stage-2 hops (fp32 out into bufC)
    k_spmm256t<0><<<sblocks, 128>>>(h16B, bufC + HH, (__half*)0, h16C);
    k_spmm128t<0><<<sblocks, 128>>>(h16C, bufC + 2 * HH, (__half*)0);

    // final
    k_final<<<(NN + FROWS - 1) / FROWS, 128>>>(bufC, b2, wf, bf, out);

    (void)in_sizes; (void)n_in; (void)out_size;
}

// round 9
// speedup vs baseline: 1.4588x; 1.0522x over previous
#include <cuda_runtime.h>
#include <cuda_fp16.h>
#include <math.h>
#include <stdint.h>

// Problem constants
#define NN 50000
#define EE 800000
#define F_IN 512
#define HH 128
#define CC 16
#define LD3H 384   // 3*H

// ---------------- device scratch (static, no allocations) ----------------
__device__ int    g_count[NN];
__device__ int    g_rowptr[NN + 1];
__device__ int    g_pos[NN];
__device__ int    g_state[64];
__device__ int    g_col[EE];
__device__ float  g_val[EE];
__device__ float  g_bufC[(size_t)NN * LD3H];   // stage-2 result (fp32, for final)
__device__ __half g_xh[(size_t)NN * F_IN];     // x in fp16
__device__ __half g_a1h[(size_t)NN * LD3H];    // a1 in fp16 (ld 384)
__device__ __half g_h16B[(size_t)NN * 256];    // GEMM out blocks 1,2 (fp16, ld 256)
__device__ __half g_h16C[(size_t)NN * 128];    // mid-hop block2 (fp16, ld 128)
__device__ __half g_w1h[3 * 128 * F_IN];       // w1^T fp16 [3][128 n][512 k]
__device__ __half g_w2h[3 * 128 * LD3H];       // w2^T fp16 [3][128 n][384 k]

// ---------------- helpers ----------------
__device__ __forceinline__ void mma_f16(float* c, const uint32_t* a, const uint32_t* b) {
    asm volatile(
        "mma.sync.aligned.m16n8k16.row.col.f32.f16.f16.f32 "
        "{%0,%1,%2,%3}, {%4,%5,%6,%7}, {%8,%9}, {%0,%1,%2,%3};\n"
        : "+f"(c[0]), "+f"(c[1]), "+f"(c[2]), "+f"(c[3])
        : "r"(a[0]), "r"(a[1]), "r"(a[2]), "r"(a[3]), "r"(b[0]), "r"(b[1]));
}

__device__ __forceinline__ void cpa16(uint32_t dst_smem, const void* src, int valid) {
    asm volatile("cp.async.cg.shared.global [%0], [%1], 16, %2;\n"
                 :: "r"(dst_smem), "l"(src), "r"(valid ? 16 : 0));
}
__device__ __forceinline__ void cpa_commit() { asm volatile("cp.async.commit_group;\n"); }
__device__ __forceinline__ void cpa_wait0()  { asm volatile("cp.async.wait_group 0;\n"); }

// ---------------- prep: x -> fp16 ----------------
#define NXE ((size_t)NN * F_IN)   // 25,600,000
__global__ void k_xhalf(const float4* __restrict__ x)
{
    size_t i = (size_t)blockIdx.x * blockDim.x + threadIdx.x;   // 8 floats each
    if (i * 8 >= NXE) return;
    float4 v0 = x[i * 2];
    float4 v1 = x[i * 2 + 1];
    __half2 h[4];
    h[0] = __floats2half2_rn(v0.x, v0.y);
    h[1] = __floats2half2_rn(v0.z, v0.w);
    h[2] = __floats2half2_rn(v1.x, v1.y);
    h[3] = __floats2half2_rn(v1.z, v1.w);
    *(uint4*)(g_xh + i * 8) = *(uint4*)h;
}

// ---------------- prep: W [3][K][128] -> W^T fp16 [3][128][K] ----------------
__global__ void k_wth(const float* __restrict__ W, __half* __restrict__ WT, int K)
{
    __shared__ float t[32][33];
    int z  = blockIdx.z;
    int k0 = blockIdx.x * 32;
    int n0 = blockIdx.y * 32;
    int tx = threadIdx.x, ty = threadIdx.y;  // 32 x 8
    #pragma unroll
    for (int i = 0; i < 4; i++) {
        int k = k0 + ty + i * 8;
        t[ty + i * 8][tx] = W[(size_t)z * K * 128 + (size_t)k * 128 + n0 + tx];
    }
    __syncthreads();
    #pragma unroll
    for (int i = 0; i < 4; i++) {
        int n = n0 + ty + i * 8;
        WT[(size_t)z * 128 * K + (size_t)n * K + k0 + tx] = __float2half_rn(t[tx][ty + i * 8]);
    }
}

// ---------------- CSR build ----------------
__global__ void k_zero_counts() {
    int i = blockIdx.x * blockDim.x + threadIdx.x;
    if (i < NN) g_count[i] = 0;
    if (i < 64) g_state[i] = -1;
}

__global__ void k_count(const int* __restrict__ idx) {
    int e = blockIdx.x * blockDim.x + threadIdx.x;
    if (e < EE) atomicAdd(&g_count[idx[e]], 1);
}

#define SCAN_B 1024
__global__ void k_scanfused() {
    __shared__ int s[SCAN_B];
    __shared__ int pfx;
    int t = threadIdx.x;
    int b = blockIdx.x;
    int i = b * SCAN_B + t;
    int v = (i < NN) ? g_count[i] : 0;
    s[t] = v;
    __syncthreads();
    #pragma unroll
    for (int o = 1; o < SCAN_B; o <<= 1) {
        int u = (t >= o) ? s[t - o] : 0;
        __syncthreads();
        s[t] += u;
        __syncthreads();
    }
    if (t == 0) {
        int total = s[SCAN_B - 1];
        int p = 0;
        if (b > 0) {
            while ((p = atomicAdd(&g_state[b - 1], 0)) < 0) {}
        }
        pfx = p;
        __threadfence();
        atomicExch(&g_state[b], p + total);
    }
    __syncthreads();
    if (i < NN) {
        int e = pfx + s[t] - v;
        g_rowptr[i] = e;
        g_pos[i] = e;
    }
    if (i == 0) g_rowptr[NN] = EE;
}

__global__ void k_scatter(const int* __restrict__ idx, const float* __restrict__ vals) {
    int e = blockIdx.x * blockDim.x + threadIdx.x;
    if (e < EE) {
        int r = idx[e];
        int p = atomicAdd(&g_pos[r], 1);
        g_col[p] = idx[EE + e];
        g_val[p] = vals[e];
    }
}

// ---------------- fp16 tensor-core GEMM (m16n8k16), BK=64, double-buffered ----------------
#define AH_LD 72                        // halves per smem row (64 + 8 pad)
#define AH_BUF (128 * AH_LD)            // halves per buffer
#define GH_SMEM_BYTES (4 * AH_BUF * 2)  // 2 bufs x (A+B) = 73728 B

__global__ __launch_bounds__(256, 2)
void k_gemm_h(const __half* __restrict__ A, int lda,
              const __half* __restrict__ Bt,
              const float* __restrict__ bias,
              float* __restrict__ C0f, __half* __restrict__ C0h,
              __half* __restrict__ Hout,
              int M, int K, int do_relu)
{
    extern __shared__ __half smh[];
    __half* As = smh;                       // [2][128][AH_LD]
    __half* Bs = smh + 2 * AH_BUF;          // [2][128][AH_LD]

    const int nb = blockIdx.x;
    const __half* B = Bt + (size_t)nb * 128 * K;
    const float* bi = bias ? (bias + nb * 128) : (const float*)0;

    const int m0   = blockIdx.y * 128;
    const int tid  = threadIdx.x;
    const int lane = tid & 31;
    const int wid  = tid >> 5;
    const int wm0  = (wid & 1) * 64;
    const int wn0  = (wid >> 1) * 32;
    const int gp   = lane >> 2;
    const int tg   = lane & 3;

    float acc[4][4][4];
    #pragma unroll
    for (int i = 0; i < 4; i++)
        #pragma unroll
        for (int j = 0; j < 4; j++)
            #pragma unroll
            for (int q = 0; q < 4; q++) acc[i][j][q] = 0.f;

    const int nk = K >> 6;   // k64 iterations

    auto stage = [&](int kt, int buf) {
        const int k0 = kt << 6;
        uint32_t abase = (uint32_t)__cvta_generic_to_shared(As + buf * AH_BUF);
        uint32_t bbase = (uint32_t)__cvta_generic_to_shared(Bs + buf * AH_BUF);
        #pragma unroll
        for (int s = 0; s < 4; s++) {
            int idx = s * 256 + tid;          // 0..1023
            int r = idx >> 3;                 // 0..127
            int c = (idx & 7) * 8;            // halves 0..56
            int gr = m0 + r;
            int ok = gr < M;
            int sr = ok ? gr : (M - 1);
            cpa16(abase + (r * AH_LD + c) * 2, A + (size_t)sr * lda + k0 + c, ok);
        }
        #pragma unroll
        for (int s = 0; s < 4; s++) {
            int idx = s * 256 + tid;
            int r = idx >> 3;
            int c = (idx & 7) * 8;
            cpa16(bbase + (r * AH_LD + c) * 2, B + (size_t)r * K + k0 + c, 1);
        }
        cpa_commit();
    };

    stage(0, 0);

    for (int kt = 0; kt < nk; kt++) {
        cpa_wait0();
        __syncthreads();
        if (kt + 1 < nk) stage(kt + 1, (kt + 1) & 1);

        const __half* Ab = As + (kt & 1) * AH_BUF;
        const __half* Bb = Bs + (kt & 1) * AH_BUF;

        #pragma unroll
        for (int ks = 0; ks < 4; ks++) {
            const int kk = ks * 16 + 2 * tg;
            uint32_t af[4][4], bf[4][2];
            #pragma unroll
            for (int i = 0; i < 4; i++) {
                int r = wm0 + i * 16 + gp;
                af[i][0] = *(const uint32_t*)&Ab[r * AH_LD + kk];
                af[i][1] = *(const uint32_t*)&Ab[(r + 8) * AH_LD + kk];
                af[i][2] = *(const uint32_t*)&Ab[r * AH_LD + kk + 8];
                af[i][3] = *(const uint32_t*)&Ab[(r + 8) * AH_LD + kk + 8];
            }
            #pragma unroll
            for (int j = 0; j < 4; j++) {
                int n = wn0 + j * 8 + gp;
                bf[j][0] = *(const uint32_t*)&Bb[n * AH_LD + kk];
                bf[j][1] = *(const uint32_t*)&Bb[n * AH_LD + kk + 8];
            }
            #pragma unroll
            for (int i = 0; i < 4; i++)
                #pragma unroll
                for (int j = 0; j < 4; j++)
                    mma_f16(acc[i][j], af[i], bf[j]);
        }
        __syncthreads();
    }

    #pragma unroll
    for (int i = 0; i < 4; i++) {
        #pragma unroll
        for (int rr = 0; rr < 2; rr++) {
            int row = m0 + wm0 + i * 16 + gp + rr * 8;
            if (row >= M) continue;
            #pragma unroll
            for (int j = 0; j < 4; j++) {
                int col = wn0 + j * 8 + 2 * tg;
                float2 v;
                v.x = acc[i][j][rr * 2 + 0];
                v.y = acc[i][j][rr * 2 + 1];
                if (bi) { v.x += bi[col]; v.y += bi[col + 1]; }
                if (do_relu) { v.x = fmaxf(v.x, 0.f); v.y = fmaxf(v.y, 0.f); }
                if (nb == 0) {
                    if (C0f) {
                        *(float2*)(C0f + (size_t)row * LD3H + col) = v;
                    } else {
                        *(__half2*)(C0h + (size_t)row * LD3H + col) =
                            __floats2half2_rn(v.x, v.y);
                    }
                } else {
                    *(__half2*)(Hout + (size_t)row * 256 + (nb - 1) * 128 + col) =
                        __floats2half2_rn(v.x, v.y);
                }
            }
        }
    }
}

// ---------------- SpMM (CSR gather, fp16 sources) ----------------
#define ACC8(av, hv, vv) do { \
    const __half2* _h = (const __half2*)&(hv); \
    _Pragma("unroll") \
    for (int _k = 0; _k < 4; _k++) { \
        float2 _f = __half22float2(_h[_k]); \
        (av)[2 * _k]     = fmaf((vv), _f.x, (av)[2 * _k]); \
        (av)[2 * _k + 1] = fmaf((vv), _f.y, (av)[2 * _k + 1]); \
    } \
} while (0)

// 256-wide: lane reads 8 halves (16B); unroll x4 for MLP.
// lanes 0-15 -> block1 (OUT16? fp16 dstH1 : fp32 dstF), lanes 16-31 -> block2 (dstH2)
template<int OUT16>
__global__ void k_spmm256t(const __half* __restrict__ src,
                           float* __restrict__ dstF, __half* __restrict__ dstH1,
                           __half* __restrict__ dstH2)
{
    int warp = (blockIdx.x * blockDim.x + threadIdx.x) >> 5;
    int lane = threadIdx.x & 31;
    if (warp >= NN) return;
    int s = g_rowptr[warp];
    int e = g_rowptr[warp + 1];
    float a[8];
    #pragma unroll
    for (int q = 0; q < 8; q++) a[q] = 0.f;
    int p = s;
    for (; p + 3 < e; p += 4) {
        int   c0 = g_col[p],     c1 = g_col[p + 1];
        int   c2 = g_col[p + 2], c3 = g_col[p + 3];
        float v0 = g_val[p],     v1 = g_val[p + 1];
        float v2 = g_val[p + 2], v3 = g_val[p + 3];
        uint4 q0 = *(const uint4*)(src + (size_t)c0 * 256 + lane * 8);
        uint4 q1 = *(const uint4*)(src + (size_t)c1 * 256 + lane * 8);
        uint4 q2 = *(const uint4*)(src + (size_t)c2 * 256 + lane * 8);
        uint4 q3 = *(const uint4*)(src + (size_t)c3 * 256 + lane * 8);
        ACC8(a, q0, v0); ACC8(a, q1, v1); ACC8(a, q2, v2); ACC8(a, q3, v3);
    }
    for (; p < e; p++) {
        int c0 = g_col[p];
        float v0 = g_val[p];
        uint4 q0 = *(const uint4*)(src + (size_t)c0 * 256 + lane * 8);
        ACC8(a, q0, v0);
    }
    if (lane < 16) {
        if (OUT16) {
            __half2 h[4];
            #pragma unroll
            for (int k = 0; k < 4; k++) h[k] = __floats2half2_rn(a[2 * k], a[2 * k + 1]);
            *(uint4*)(dstH1 + (size_t)warp * LD3H + lane * 8) = *(uint4*)h;
        } else {
            float* d = dstF + (size_t)warp * LD3H + lane * 8;
            *(float4*)d       = make_float4(a[0], a[1], a[2], a[3]);
            *(float4*)(d + 4) = make_float4(a[4], a[5], a[6], a[7]);
        }
    } else {
        __half2 h[4];
        #pragma unroll
        for (int k = 0; k < 4; k++) h[k] = __floats2half2_rn(a[2 * k], a[2 * k + 1]);
        *(uint4*)(dstH2 + (size_t)warp * 128 + (lane - 16) * 8) = *(uint4*)h;
    }
}

// 128-wide: 2 rows per warp (16 lanes x 8 halves = 16B loads); unroll x4.
template<int OUT16>
__global__ void k_spmm128t(const __half* __restrict__ src,
                           float* __restrict__ dstF, __half* __restrict__ dstH)
{
    int warp = (blockIdx.x * blockDim.x + threadIdx.x) >> 5;
    int lane = threadIdx.x & 31;
    int row = 2 * warp + (lane >> 4);
    int sub = lane & 15;
    if (row >= NN) return;
    int s = g_rowptr[row];
    int e = g_rowptr[row + 1];
    float a[8];
    #pragma unroll
    for (int q = 0; q < 8; q++) a[q] = 0.f;
    int p = s;
    for (; p + 3 < e; p += 4) {
        int   c0 = g_col[p],     c1 = g_col[p + 1];
        int   c2 = g_col[p + 2], c3 = g_col[p + 3];
        float v0 = g_val[p],     v1 = g_val[p + 1];
        float v2 = g_val[p + 2], v3 = g_val[p + 3];
        uint4 q0 = *(const uint4*)(src + (size_t)c0 * 128 + sub * 8);
        uint4 q1 = *(const uint4*)(src + (size_t)c1 * 128 + sub * 8);
        uint4 q2 = *(const uint4*)(src + (size_t)c2 * 128 + sub * 8);
        uint4 q3 = *(const uint4*)(src + (size_t)c3 * 128 + sub * 8);
        ACC8(a, q0, v0); ACC8(a, q1, v1); ACC8(a, q2, v2); ACC8(a, q3, v3);
    }
    for (; p < e; p++) {
        int c0 = g_col[p];
        float v0 = g_val[p];
        uint4 q0 = *(const uint4*)(src + (size_t)c0 * 128 + sub * 8);
        ACC8(a, q0, v0);
    }
    if (OUT16) {
        __half2 h[4];
        #pragma unroll
        for (int k = 0; k < 4; k++) h[k] = __floats2half2_rn(a[2 * k], a[2 * k + 1]);
        *(uint4*)(dstH + (size_t)row * LD3H + sub * 8) = *(uint4*)h;
    } else {
        float* d = dstF + (size_t)row * LD3H + sub * 8;
        *(float4*)d       = make_float4(a[0], a[1], a[2], a[3]);
        *(float4*)(d + 4) = make_float4(a[4], a[5], a[6], a[7]);
    }
}

// ---------------- final ----------------
#define FROWS 8
__global__ __launch_bounds__(128)
void k_final(const float* __restrict__ g,
             const float* __restrict__ b2,
             const float* __restrict__ wf,
             const float* __restrict__ bfv,
             float* __restrict__ out)
{
    __shared__ float wfs[LD3H * CC];
    __shared__ float gs[FROWS][LD3H];
    int tid = threadIdx.x;
    for (int i = tid; i < LD3H * CC; i += 128) wfs[i] = wf[i];
    int row0 = blockIdx.x * FROWS;
    for (int i = tid; i < FROWS * LD3H; i += 128) {
        int r = i / LD3H, k = i % LD3H;
        int gr = row0 + r;
        gs[r][k] = (gr < NN) ? g[(size_t)gr * LD3H + k] + b2[k] : 0.f;
    }
    __syncthreads();

    int r = tid >> 4;
    int c = tid & 15;
    float acc = bfv[c];
    #pragma unroll 8
    for (int k = 0; k < LD3H; k++) acc = fmaf(gs[r][k], wfs[k * CC + c], acc);

    float m = acc;
    #pragma unroll
    for (int o = 8; o >= 1; o >>= 1) m = fmaxf(m, __shfl_xor_sync(0xffffffffu, m, o, 16));
    float ex = __expf(acc - m);
    float s = ex;
    #pragma unroll
    for (int o = 8; o >= 1; o >>= 1) s += __shfl_xor_sync(0xffffffffu, s, o, 16);
    int gr = row0 + r;
    if (gr < NN) out[gr * CC + c] = acc - m - logf(s);
}

// ---------------- launch ----------------
extern "C" void kernel_launch(void* const* d_in, const int* in_sizes, int n_in,
                              void* d_out, int out_size)
{
    const float* x   = (const float*)d_in[0];
    const int*   adj = (const int*)d_in[1];
    const float* av  = (const float*)d_in[2];
    const float* w1  = (const float*)d_in[3];
    const float* b1  = (const float*)d_in[4];
    const float* w2  = (const float*)d_in[5];
    const float* b2  = (const float*)d_in[6];
    const float* wf  = (const float*)d_in[7];
    const float* bf  = (const float*)d_in[8];
    float* out = (float*)d_out;

    float *bufC;
    __half *xh, *a1h, *h16B, *h16C, *w1h, *w2h;
    cudaGetSymbolAddress((void**)&bufC, g_bufC);
    cudaGetSymbolAddress((void**)&xh,   g_xh);
    cudaGetSymbolAddress((void**)&a1h,  g_a1h);
    cudaGetSymbolAddress((void**)&h16B, g_h16B);
    cudaGetSymbolAddress((void**)&h16C, g_h16C);
    cudaGetSymbolAddress((void**)&w1h,  g_w1h);
    cudaGetSymbolAddress((void**)&w2h,  g_w2h);

    cudaFuncSetAttribute(k_gemm_h, cudaFuncAttributeMaxDynamicSharedMemorySize,
                         GH_SMEM_BYTES);

    static cudaStream_t s2 = 0;
    static cudaEvent_t evFork = 0, evCSR = 0;
    if (!s2) {
        cudaStreamCreateWithFlags(&s2, cudaStreamNonBlocking);
        cudaEventCreateWithFlags(&evFork, cudaEventDisableTiming);
        cudaEventCreateWithFlags(&evCSR,  cudaEventDisableTiming);
    }

    const int nscan = (NN + SCAN_B - 1) / SCAN_B;   // 49
    const int mtiles = (NN + 127) / 128;            // 391
    const int sblocks = (NN + 3) / 4;               // spmm256: warp per row
    const int sblocks2 = (NN / 2 + 3) / 4;          // spmm128: warp per 2 rows

    // ---- fork: CSR on s2 ----
    cudaEventRecord(evFork, 0);
    cudaStreamWaitEvent(s2, evFork, 0);
    k_zero_counts<<<(NN + 255) / 256, 256, 0, s2>>>();
    k_count<<<(EE + 255) / 256, 256, 0, s2>>>(adj);
    k_scanfused<<<nscan, SCAN_B, 0, s2>>>();
    k_scatter<<<(EE + 255) / 256, 256, 0, s2>>>(adj, av);
    cudaEventRecord(evCSR, s2);

    // s0: prep (x->fp16, weights->fp16 transposed)
    k_xhalf<<<(unsigned)((NXE / 8 + 255) / 256), 256>>>((const float4*)x);
    k_wth<<<dim3(F_IN / 32, 4, 3), dim3(32, 8)>>>(w1, w1h, F_IN);
    k_wth<<<dim3(LD3H / 32, 4, 3), dim3(32, 8)>>>(w2, w2h, LD3H);

    // GEMM1: block0 -> a1h fp16; blocks 1,2 -> h16B fp16
    k_gemm_h<<<dim3(3, mtiles), 256, GH_SMEM_BYTES>>>(
        xh, F_IN, w1h, b1, (float*)0, a1h, h16B, NN, F_IN, 1);

    // join: spmm needs CSR
    cudaStreamWaitEvent(0, evCSR, 0);

    // stage-1 hops (all fp16 out)
    k_spmm256t<1><<<sblocks, 128>>>(h16B, (float*)0, a1h + HH, h16C);
    k_spmm128t<1><<<sblocks2, 128>>>(h16C, (float*)0, a1h + 2 * HH);

    // GEMM2: block0 -> bufC fp32; blocks 1,2 -> h16B fp16 (bias deferred)
    k_gemm_h<<<dim3(3, mtiles), 256, GH_SMEM_BYTES>>>(
        a1h, LD3H, w2h, (const float*)0, bufC, (__half*)0, h16B, NN, LD3H, 0);

    // stage-2 hops (fp32 out into bufC)
    k_spmm256t<0><<<sblocks, 128>>>(h16B, bufC + HH, (__half*)0, h16C);
    k_spmm128t<0><<<sblocks2, 128>>>(h16C, bufC + 2 * HH, (__half*)0);

    // final
    k_final<<<(NN + FROWS - 1) / FROWS, 128>>>(bufC, b2, wf, bf, out);

    (void)in_sizes; (void)n_in; (void)out_size;
}

// round 10
// speedup vs baseline: 1.6677x; 1.1432x over previous
#include <cuda_runtime.h>
#include <cuda_fp16.h>
#include <math.h>
#include <stdint.h>

// Problem constants
#define NN 50000
#define EE 800000
#define F_IN 512
#define HH 128
#define CC 16
#define LD3H 384   // 3*H

// ---------------- device scratch (static, no allocations) ----------------
__device__ int    g_count[NN];
__device__ int    g_rowptr[NN + 1];
__device__ int    g_pos[NN];
__device__ int    g_state[64];
__device__ int    g_col[EE];
__device__ float  g_val[EE];
__device__ __half g_xh[(size_t)NN * F_IN];     // x in fp16
__device__ __half g_a1h[(size_t)NN * LD3H];    // a1 in fp16 (ld 384)
__device__ __half g_g2h[(size_t)NN * LD3H];    // stage-2 result in fp16 (ld 384)
__device__ __half g_h16B[(size_t)NN * 256];    // GEMM out blocks 1,2 (fp16, ld 256)
__device__ __half g_h16C[(size_t)NN * 128];    // mid-hop block2 (fp16, ld 128)
__device__ __half g_w1h[3 * 128 * F_IN];       // w1^T fp16 [3][128 n][512 k]
__device__ __half g_w2h[3 * 128 * LD3H];       // w2^T fp16 [3][128 n][384 k]

// ---------------- helpers ----------------
__device__ __forceinline__ void mma_f16(float* c, const uint32_t* a, const uint32_t* b) {
    asm volatile(
        "mma.sync.aligned.m16n8k16.row.col.f32.f16.f16.f32 "
        "{%0,%1,%2,%3}, {%4,%5,%6,%7}, {%8,%9}, {%0,%1,%2,%3};\n"
        : "+f"(c[0]), "+f"(c[1]), "+f"(c[2]), "+f"(c[3])
        : "r"(a[0]), "r"(a[1]), "r"(a[2]), "r"(a[3]), "r"(b[0]), "r"(b[1]));
}

__device__ __forceinline__ void cpa16(uint32_t dst_smem, const void* src, int valid) {
    asm volatile("cp.async.cg.shared.global [%0], [%1], 16, %2;\n"
                 :: "r"(dst_smem), "l"(src), "r"(valid ? 16 : 0));
}
__device__ __forceinline__ void cpa_commit() { asm volatile("cp.async.commit_group;\n"); }
__device__ __forceinline__ void cpa_wait0()  { asm volatile("cp.async.wait_group 0;\n"); }

// ---------------- prep: x -> fp16 ----------------
#define NXE ((size_t)NN * F_IN)   // 25,600,000
__global__ void k_xhalf(const float4* __restrict__ x)
{
    size_t i = (size_t)blockIdx.x * blockDim.x + threadIdx.x;   // 8 floats each
    if (i * 8 >= NXE) return;
    float4 v0 = x[i * 2];
    float4 v1 = x[i * 2 + 1];
    __half2 h[4];
    h[0] = __floats2half2_rn(v0.x, v0.y);
    h[1] = __floats2half2_rn(v0.z, v0.w);
    h[2] = __floats2half2_rn(v1.x, v1.y);
    h[3] = __floats2half2_rn(v1.z, v1.w);
    *(uint4*)(g_xh + i * 8) = *(uint4*)h;
}

// ---------------- prep: W1 and W2 [3][K][128] -> W^T fp16 [3][128][K] ----------------
// z in [0,3): w1 (K=512); z in [3,6): w2 (K=384)
__global__ void k_wth2(const float* __restrict__ W1, const float* __restrict__ W2)
{
    __shared__ float t[32][33];
    int zz = blockIdx.z;
    int is2 = zz >= 3;
    int z  = is2 ? zz - 3 : zz;
    int K  = is2 ? LD3H : F_IN;
    const float* W = is2 ? W2 : W1;
    __half* WT = is2 ? g_w2h : g_w1h;
    int k0 = blockIdx.x * 32;
    if (k0 >= K) return;
    int n0 = blockIdx.y * 32;
    int tx = threadIdx.x, ty = threadIdx.y;  // 32 x 8
    #pragma unroll
    for (int i = 0; i < 4; i++) {
        int k = k0 + ty + i * 8;
        t[ty + i * 8][tx] = W[(size_t)z * K * 128 + (size_t)k * 128 + n0 + tx];
    }
    __syncthreads();
    #pragma unroll
    for (int i = 0; i < 4; i++) {
        int n = n0 + ty + i * 8;
        WT[(size_t)z * 128 * K + (size_t)n * K + k0 + tx] = __float2half_rn(t[tx][ty + i * 8]);
    }
}

// ---------------- CSR build ----------------
__global__ void k_zero_counts() {
    int i = blockIdx.x * blockDim.x + threadIdx.x;
    if (i < NN) g_count[i] = 0;
    if (i < 64) g_state[i] = -1;
}

__global__ void k_count(const int* __restrict__ idx) {
    int e = blockIdx.x * blockDim.x + threadIdx.x;
    if (e < EE) atomicAdd(&g_count[idx[e]], 1);
}

#define SCAN_B 1024
__global__ void k_scanfused() {
    __shared__ int s[SCAN_B];
    __shared__ int pfx;
    int t = threadIdx.x;
    int b = blockIdx.x;
    int i = b * SCAN_B + t;
    int v = (i < NN) ? g_count[i] : 0;
    s[t] = v;
    __syncthreads();
    #pragma unroll
    for (int o = 1; o < SCAN_B; o <<= 1) {
        int u = (t >= o) ? s[t - o] : 0;
        __syncthreads();
        s[t] += u;
        __syncthreads();
    }
    if (t == 0) {
        int total = s[SCAN_B - 1];
        int p = 0;
        if (b > 0) {
            while ((p = atomicAdd(&g_state[b - 1], 0)) < 0) {}
        }
        pfx = p;
        __threadfence();
        atomicExch(&g_state[b], p + total);
    }
    __syncthreads();
    if (i < NN) {
        int e = pfx + s[t] - v;
        g_rowptr[i] = e;
        g_pos[i] = e;
    }
    if (i == 0) g_rowptr[NN] = EE;
}

__global__ void k_scatter(const int* __restrict__ idx, const float* __restrict__ vals) {
    int e = blockIdx.x * blockDim.x + threadIdx.x;
    if (e < EE) {
        int r = idx[e];
        int p = atomicAdd(&g_pos[r], 1);
        g_col[p] = idx[EE + e];
        g_val[p] = vals[e];
    }
}

// ---------------- fp16 tensor-core GEMM (m16n8k16), BK=64, double-buffered ----------------
#define AH_LD 72
#define AH_BUF (128 * AH_LD)
#define GH_SMEM_BYTES (4 * AH_BUF * 2)  // 73728 B

__global__ __launch_bounds__(256, 2)
void k_gemm_h(const __half* __restrict__ A, int lda,
              const __half* __restrict__ Bt,
              const float* __restrict__ bias,
              float* __restrict__ C0f, __half* __restrict__ C0h,
              __half* __restrict__ Hout,
              int M, int K, int do_relu)
{
    extern __shared__ __half smh[];
    __half* As = smh;
    __half* Bs = smh + 2 * AH_BUF;

    const int nb = blockIdx.x;
    const __half* B = Bt + (size_t)nb * 128 * K;
    const float* bi = bias ? (bias + nb * 128) : (const float*)0;

    const int m0   = blockIdx.y * 128;
    const int tid  = threadIdx.x;
    const int lane = tid & 31;
    const int wid  = tid >> 5;
    const int wm0  = (wid & 1) * 64;
    const int wn0  = (wid >> 1) * 32;
    const int gp   = lane >> 2;
    const int tg   = lane & 3;

    float acc[4][4][4];
    #pragma unroll
    for (int i = 0; i < 4; i++)
        #pragma unroll
        for (int j = 0; j < 4; j++)
            #pragma unroll
            for (int q = 0; q < 4; q++) acc[i][j][q] = 0.f;

    const int nk = K >> 6;

    auto stage = [&](int kt, int buf) {
        const int k0 = kt << 6;
        uint32_t abase = (uint32_t)__cvta_generic_to_shared(As + buf * AH_BUF);
        uint32_t bbase = (uint32_t)__cvta_generic_to_shared(Bs + buf * AH_BUF);
        #pragma unroll
        for (int s = 0; s < 4; s++) {
            int idx = s * 256 + tid;
            int r = idx >> 3;
            int c = (idx & 7) * 8;
            int gr = m0 + r;
            int ok = gr < M;
            int sr = ok ? gr : (M - 1);
            cpa16(abase + (r * AH_LD + c) * 2, A + (size_t)sr * lda + k0 + c, ok);
        }
        #pragma unroll
        for (int s = 0; s < 4; s++) {
            int idx = s * 256 + tid;
            int r = idx >> 3;
            int c = (idx & 7) * 8;
            cpa16(bbase + (r * AH_LD + c) * 2, B + (size_t)r * K + k0 + c, 1);
        }
        cpa_commit();
    };

    stage(0, 0);

    for (int kt = 0; kt < nk; kt++) {
        cpa_wait0();
        __syncthreads();
        if (kt + 1 < nk) stage(kt + 1, (kt + 1) & 1);

        const __half* Ab = As + (kt & 1) * AH_BUF;
        const __half* Bb = Bs + (kt & 1) * AH_BUF;

        #pragma unroll
        for (int ks = 0; ks < 4; ks++) {
            const int kk = ks * 16 + 2 * tg;
            uint32_t af[4][4], bf[4][2];
            #pragma unroll
            for (int i = 0; i < 4; i++) {
                int r = wm0 + i * 16 + gp;
                af[i][0] = *(const uint32_t*)&Ab[r * AH_LD + kk];
                af[i][1] = *(const uint32_t*)&Ab[(r + 8) * AH_LD + kk];
                af[i][2] = *(const uint32_t*)&Ab[r * AH_LD + kk + 8];
                af[i][3] = *(const uint32_t*)&Ab[(r + 8) * AH_LD + kk + 8];
            }
            #pragma unroll
            for (int j = 0; j < 4; j++) {
                int n = wn0 + j * 8 + gp;
                bf[j][0] = *(const uint32_t*)&Bb[n * AH_LD + kk];
                bf[j][1] = *(const uint32_t*)&Bb[n * AH_LD + kk + 8];
            }
            #pragma unroll
            for (int i = 0; i < 4; i++)
                #pragma unroll
                for (int j = 0; j < 4; j++)
                    mma_f16(acc[i][j], af[i], bf[j]);
        }
        __syncthreads();
    }

    #pragma unroll
    for (int i = 0; i < 4; i++) {
        #pragma unroll
        for (int rr = 0; rr < 2; rr++) {
            int row = m0 + wm0 + i * 16 + gp + rr * 8;
            if (row >= M) continue;
            #pragma unroll
            for (int j = 0; j < 4; j++) {
                int col = wn0 + j * 8 + 2 * tg;
                float2 v;
                v.x = acc[i][j][rr * 2 + 0];
                v.y = acc[i][j][rr * 2 + 1];
                if (bi) { v.x += bi[col]; v.y += bi[col + 1]; }
                if (do_relu) { v.x = fmaxf(v.x, 0.f); v.y = fmaxf(v.y, 0.f); }
                if (nb == 0) {
                    if (C0f) {
                        *(float2*)(C0f + (size_t)row * LD3H + col) = v;
                    } else {
                        *(__half2*)(C0h + (size_t)row * LD3H + col) =
                            __floats2half2_rn(v.x, v.y);
                    }
                } else {
                    *(__half2*)(Hout + (size_t)row * 256 + (nb - 1) * 128 + col) =
                        __floats2half2_rn(v.x, v.y);
                }
            }
        }
    }
}

// ---------------- SpMM (CSR gather, fp16 sources) ----------------
#define ACC8(av, hv, vv) do { \
    const __half2* _h = (const __half2*)&(hv); \
    _Pragma("unroll") \
    for (int _k = 0; _k < 4; _k++) { \
        float2 _f = __half22float2(_h[_k]); \
        (av)[2 * _k]     = fmaf((vv), _f.x, (av)[2 * _k]); \
        (av)[2 * _k + 1] = fmaf((vv), _f.y, (av)[2 * _k + 1]); \
    } \
} while (0)

// 256-wide: lane reads 8 halves (16B); unroll x8 then x2 then x1.
// lanes 0-15 -> block1 (OUT16? fp16 dstH1 : unused), lanes 16-31 -> block2 (dstH2)
template<int OUT16>
__global__ void k_spmm256t(const __half* __restrict__ src,
                           float* __restrict__ dstF, __half* __restrict__ dstH1,
                           __half* __restrict__ dstH2)
{
    int warp = (blockIdx.x * blockDim.x + threadIdx.x) >> 5;
    int lane = threadIdx.x & 31;
    if (warp >= NN) return;
    int s = g_rowptr[warp];
    int e = g_rowptr[warp + 1];
    float a[8];
    #pragma unroll
    for (int q = 0; q < 8; q++) a[q] = 0.f;
    int p = s;
    for (; p + 7 < e; p += 8) {
        uint4 q0 = *(const uint4*)(src + (size_t)g_col[p]     * 256 + lane * 8);
        uint4 q1 = *(const uint4*)(src + (size_t)g_col[p + 1] * 256 + lane * 8);
        uint4 q2 = *(const uint4*)(src + (size_t)g_col[p + 2] * 256 + lane * 8);
        uint4 q3 = *(const uint4*)(src + (size_t)g_col[p + 3] * 256 + lane * 8);
        uint4 q4 = *(const uint4*)(src + (size_t)g_col[p + 4] * 256 + lane * 8);
        uint4 q5 = *(const uint4*)(src + (size_t)g_col[p + 5] * 256 + lane * 8);
        uint4 q6 = *(const uint4*)(src + (size_t)g_col[p + 6] * 256 + lane * 8);
        uint4 q7 = *(const uint4*)(src + (size_t)g_col[p + 7] * 256 + lane * 8);
        ACC8(a, q0, g_val[p]);     ACC8(a, q1, g_val[p + 1]);
        ACC8(a, q2, g_val[p + 2]); ACC8(a, q3, g_val[p + 3]);
        ACC8(a, q4, g_val[p + 4]); ACC8(a, q5, g_val[p + 5]);
        ACC8(a, q6, g_val[p + 6]); ACC8(a, q7, g_val[p + 7]);
    }
    for (; p + 1 < e; p += 2) {
        uint4 q0 = *(const uint4*)(src + (size_t)g_col[p]     * 256 + lane * 8);
        uint4 q1 = *(const uint4*)(src + (size_t)g_col[p + 1] * 256 + lane * 8);
        ACC8(a, q0, g_val[p]); ACC8(a, q1, g_val[p + 1]);
    }
    if (p < e) {
        uint4 q0 = *(const uint4*)(src + (size_t)g_col[p] * 256 + lane * 8);
        ACC8(a, q0, g_val[p]);
    }
    if (lane < 16) {
        if (OUT16) {
            __half2 h[4];
            #pragma unroll
            for (int k = 0; k < 4; k++) h[k] = __floats2half2_rn(a[2 * k], a[2 * k + 1]);
            *(uint4*)(dstH1 + (size_t)warp * LD3H + lane * 8) = *(uint4*)h;
        } else {
            float* d = dstF + (size_t)warp * LD3H + lane * 8;
            *(float4*)d       = make_float4(a[0], a[1], a[2], a[3]);
            *(float4*)(d + 4) = make_float4(a[4], a[5], a[6], a[7]);
        }
    } else {
        __half2 h[4];
        #pragma unroll
        for (int k = 0; k < 4; k++) h[k] = __floats2half2_rn(a[2 * k], a[2 * k + 1]);
        *(uint4*)(dstH2 + (size_t)warp * 128 + (lane - 16) * 8) = *(uint4*)h;
    }
}

// 128-wide: 2 rows per warp (16 lanes x 8 halves); unroll x4.
template<int OUT16>
__global__ void k_spmm128t(const __half* __restrict__ src,
                           float* __restrict__ dstF, __half* __restrict__ dstH)
{
    int warp = (blockIdx.x * blockDim.x + threadIdx.x) >> 5;
    int lane = threadIdx.x & 31;
    int row = 2 * warp + (lane >> 4);
    int sub = lane & 15;
    if (row >= NN) return;
    int s = g_rowptr[row];
    int e = g_rowptr[row + 1];
    float a[8];
    #pragma unroll
    for (int q = 0; q < 8; q++) a[q] = 0.f;
    int p = s;
    for (; p + 3 < e; p += 4) {
        uint4 q0 = *(const uint4*)(src + (size_t)g_col[p]     * 128 + sub * 8);
        uint4 q1 = *(const uint4*)(src + (size_t)g_col[p + 1] * 128 + sub * 8);
        uint4 q2 = *(const uint4*)(src + (size_t)g_col[p + 2] * 128 + sub * 8);
        uint4 q3 = *(const uint4*)(src + (size_t)g_col[p + 3] * 128 + sub * 8);
        ACC8(a, q0, g_val[p]);     ACC8(a, q1, g_val[p + 1]);
        ACC8(a, q2, g_val[p + 2]); ACC8(a, q3, g_val[p + 3]);
    }
    for (; p < e; p++) {
        uint4 q0 = *(const uint4*)(src + (size_t)g_col[p] * 128 + sub * 8);
        ACC8(a, q0, g_val[p]);
    }
    if (OUT16) {
        __half2 h[4];
        #pragma unroll
        for (int k = 0; k < 4; k++) h[k] = __floats2half2_rn(a[2 * k], a[2 * k + 1]);
        *(uint4*)(dstH + (size_t)row * LD3H + sub * 8) = *(uint4*)h;
    } else {
        float* d = dstF + (size_t)row * LD3H + sub * 8;
        *(float4*)d       = make_float4(a[0], a[1], a[2], a[3]);
        *(float4*)(d + 4) = make_float4(a[4], a[5], a[6], a[7]);
    }
}

// ---------------- final: out = log_softmax((g2h + b2cat) @ wf + bf), fp16 input ----------------
#define FROWS 8
__global__ __launch_bounds__(128)
void k_final16(const __half* __restrict__ g,
               const float* __restrict__ b2,
               const float* __restrict__ wf,
               const float* __restrict__ bfv,
               float* __restrict__ out)
{
    __shared__ float wfs[LD3H * CC];
    __shared__ float gs[FROWS][LD3H];
    int tid = threadIdx.x;
    for (int i = tid; i < LD3H * CC; i += 128) wfs[i] = wf[i];
    int row0 = blockIdx.x * FROWS;
    // 1536 half2 pairs across FROWS*LD3H
    for (int j = tid; j < FROWS * LD3H / 2; j += 128) {
        int r = j / (LD3H / 2);
        int c = 2 * (j % (LD3H / 2));
        int gr = row0 + r;
        float2 f = make_float2(0.f, 0.f);
        if (gr < NN) {
            __half2 h = *(const __half2*)(g + (size_t)gr * LD3H + c);
            f = __half22float2(h);
            f.x += b2[c];
            f.y += b2[c + 1];
        }
        gs[r][c] = f.x;
        gs[r][c + 1] = f.y;
    }
    __syncthreads();

    int r = tid >> 4;
    int c = tid & 15;
    float acc = bfv[c];
    #pragma unroll 8
    for (int k = 0; k < LD3H; k++) acc = fmaf(gs[r][k], wfs[k * CC + c], acc);

    float m = acc;
    #pragma unroll
    for (int o = 8; o >= 1; o >>= 1) m = fmaxf(m, __shfl_xor_sync(0xffffffffu, m, o, 16));
    float ex = __expf(acc - m);
    float s = ex;
    #pragma unroll
    for (int o = 8; o >= 1; o >>= 1) s += __shfl_xor_sync(0xffffffffu, s, o, 16);
    int gr = row0 + r;
    if (gr < NN) out[gr * CC + c] = acc - m - logf(s);
}

// ---------------- launch ----------------
extern "C" void kernel_launch(void* const* d_in, const int* in_sizes, int n_in,
                              void* d_out, int out_size)
{
    const float* x   = (const float*)d_in[0];
    const int*   adj = (const int*)d_in[1];
    const float* av  = (const float*)d_in[2];
    const float* w1  = (const float*)d_in[3];
    const float* b1  = (const float*)d_in[4];
    const float* w2  = (const float*)d_in[5];
    const float* b2  = (const float*)d_in[6];
    const float* wf  = (const float*)d_in[7];
    const float* bf  = (const float*)d_in[8];
    float* out = (float*)d_out;

    __half *xh, *a1h, *g2h, *h16B, *h16C, *w1h, *w2h;
    cudaGetSymbolAddress((void**)&xh,   g_xh);
    cudaGetSymbolAddress((void**)&a1h,  g_a1h);
    cudaGetSymbolAddress((void**)&g2h,  g_g2h);
    cudaGetSymbolAddress((void**)&h16B, g_h16B);
    cudaGetSymbolAddress((void**)&h16C, g_h16C);
    cudaGetSymbolAddress((void**)&w1h,  g_w1h);
    cudaGetSymbolAddress((void**)&w2h,  g_w2h);

    cudaFuncSetAttribute(k_gemm_h, cudaFuncAttributeMaxDynamicSharedMemorySize,
                         GH_SMEM_BYTES);

    static cudaStream_t s2 = 0;
    static cudaEvent_t evFork = 0, evCSR = 0;
    if (!s2) {
        cudaStreamCreateWithFlags(&s2, cudaStreamNonBlocking);
        cudaEventCreateWithFlags(&evFork, cudaEventDisableTiming);
        cudaEventCreateWithFlags(&evCSR,  cudaEventDisableTiming);
    }

    const int nscan = (NN + SCAN_B - 1) / SCAN_B;   // 49
    const int mtiles = (NN + 127) / 128;            // 391
    const int sblocks = (NN + 3) / 4;               // spmm256: warp per row
    const int sblocks2 = (NN / 2 + 3) / 4;          // spmm128: warp per 2 rows

    // ---- fork: CSR on s2 ----
    cudaEventRecord(evFork, 0);
    cudaStreamWaitEvent(s2, evFork, 0);
    k_zero_counts<<<(NN + 255) / 256, 256, 0, s2>>>();
    k_count<<<(EE + 255) / 256, 256, 0, s2>>>(adj);
    k_scanfused<<<nscan, SCAN_B, 0, s2>>>();
    k_scatter<<<(EE + 255) / 256, 256, 0, s2>>>(adj, av);
    cudaEventRecord(evCSR, s2);

    // s0: prep (x->fp16, both weights->fp16 transposed in one launch)
    k_xhalf<<<(unsigned)((NXE / 8 + 255) / 256), 256>>>((const float4*)x);
    k_wth2<<<dim3(F_IN / 32, 4, 6), dim3(32, 8)>>>(w1, w2);

    // GEMM1: block0 -> a1h fp16; blocks 1,2 -> h16B fp16
    k_gemm_h<<<dim3(3, mtiles), 256, GH_SMEM_BYTES>>>(
        xh, F_IN, w1h, b1, (float*)0, a1h, h16B, NN, F_IN, 1);

    // join: spmm needs CSR
    cudaStreamWaitEvent(0, evCSR, 0);

    // stage-1 hops (all fp16 out)
    k_spmm256t<1><<<sblocks, 128>>>(h16B, (float*)0, a1h + HH, h16C);
    k_spmm128t<1><<<sblocks2, 128>>>(h16C, (float*)0, a1h + 2 * HH);

    // GEMM2: block0 -> g2h fp16; blocks 1,2 -> h16B fp16 (bias deferred)
    k_gemm_h<<<dim3(3, mtiles), 256, GH_SMEM_BYTES>>>(
        a1h, LD3H, w2h, (const float*)0, (float*)0, g2h, h16B, NN, LD3H, 0);

    // stage-2 hops (fp16 out into g2h)
    k_spmm256t<1><<<sblocks, 128>>>(h16B, (float*)0, g2h + HH, h16C);
    k_spmm128t<1><<<sblocks2, 128>>>(h16C, (float*)0, g2h + 2 * HH);

    // final (fp16 input, bias b2 added here in fp32)
    k_final16<<<(NN + FROWS - 1) / FROWS, 128>>>(g2h, b2, wf, bf, out);

    (void)in_sizes; (void)n_in; (void)out_size;
}